// round 3
// baseline (speedup 1.0000x reference)
#include <cuda_runtime.h>
#include <math.h>

#define T 96
#define B 1024
#define K 10
#define C 16
#define H 32
#define G 256
#define L 4
#define KH (K*H)   // 320
#define NB 8       // batches per GARU block

__device__ float g_h[B*G];       // GARU hidden state, carried across timesteps
__device__ float g_comb[B*KH];   // GNN output (flattened h) per timestep

__global__ void zero_h_kernel() {
    int i = blockIdx.x * blockDim.x + threadIdx.x;
    if (i < B*G) g_h[i] = 0.f;
}

// One block per batch element; 320 threads = (k, j) over [K, H].
__global__ __launch_bounds__(KH) void gnn_kernel(
    int t,
    const float* __restrict__ x, const float* __restrict__ adj,
    const float* __restrict__ W_fi, const float* __restrict__ b_fi,
    const float* __restrict__ Wz, const float* __restrict__ Uz, const float* __restrict__ bz,
    const float* __restrict__ Wr, const float* __restrict__ Ur, const float* __restrict__ br,
    const float* __restrict__ Wh, const float* __restrict__ Uh, const float* __restrict__ bh)
{
    __shared__ float sx[K*C];
    __shared__ float sadj[K*K];
    __shared__ float sdeg[K];
    __shared__ float sh[K*H];
    __shared__ float sh0[K*H];
    __shared__ float sm[K*H];
    __shared__ float srh[K*H];

    const int b   = blockIdx.x;
    const int tid = threadIdx.x;
    const int k   = tid >> 5;     // node index (H == 32)
    const int j   = tid & 31;     // hidden index

    // Load x_t[b] and adj_t[b] (+ self loops)
    if (tid < K*C) sx[tid] = x[(size_t)(t*B + b)*(K*C) + tid];
    if (tid < K*K) {
        int row = tid / K, col = tid - row*K;
        sadj[tid] = adj[(size_t)(t*B + b)*(K*K) + tid] + (row == col ? 1.f : 0.f);
    }
    __syncthreads();
    if (tid < K) {
        float s = 0.f;
        #pragma unroll
        for (int i = 0; i < K; i++) s += sadj[tid*K + i];
        sdeg[tid] = 1.f / (s + 1e-6f);
    }
    __syncthreads();
    if (tid < K*K) sadj[tid] *= sdeg[tid / K];

    // h0 = x @ W_fi + b_fi
    float acc = b_fi[j];
    #pragma unroll
    for (int c = 0; c < C; c++) acc += sx[k*C + c] * W_fi[c*H + j];
    sh0[tid] = acc;
    sh[tid]  = acc;
    __syncthreads();

    for (int l = 0; l < L; l++) {
        const float* Wzl = Wz + l*H*H; const float* Uzl = Uz + l*H*H;
        const float* Wrl = Wr + l*H*H; const float* Url = Ur + l*H*H;
        const float* Whl = Wh + l*H*H; const float* Uhl = Uh + l*H*H;

        // m = adj_norm @ h
        float m = 0.f;
        #pragma unroll
        for (int i = 0; i < K; i++) m += sadj[k*K + i] * sh[i*H + j];
        sm[tid] = m;
        __syncthreads();

        // z, r gates
        float az = bz[l*H + j];
        float ar = br[l*H + j];
        #pragma unroll 8
        for (int i = 0; i < H; i++) {
            float mv = sm[k*H + i], hv = sh[k*H + i];
            az += mv * Wzl[i*H + j] + hv * Uzl[i*H + j];
            ar += mv * Wrl[i*H + j] + hv * Url[i*H + j];
        }
        float z = 1.f / (1.f + expf(-az));
        float r = 1.f / (1.f + expf(-ar));
        srh[tid] = r * sh[tid];
        __syncthreads();

        // n gate
        float an = bh[l*H + j];
        #pragma unroll 8
        for (int i = 0; i < H; i++)
            an += sm[k*H + i] * Whl[i*H + j] + srh[k*H + i] * Uhl[i*H + j];
        float n = tanhf(an);

        float hn = (1.f - z) * sh[tid] + z * n + sh0[tid];
        __syncthreads();
        sh[tid] = hn;
        __syncthreads();
    }

    // comb = h.reshape(K*H), layout k*H + j == tid
    g_comb[(size_t)b*KH + tid] = sh[tid];
}

// One block handles NB=8 batch elements; 256 threads = output column g.
__global__ __launch_bounds__(G) void garu_kernel(
    const float* __restrict__ Wgp, const float* __restrict__ bgp,
    const float* __restrict__ Wgz, const float* __restrict__ Ugz, const float* __restrict__ bgz,
    const float* __restrict__ Wgr, const float* __restrict__ Ugr, const float* __restrict__ bgr,
    const float* __restrict__ Wgn, const float* __restrict__ Ugn, const float* __restrict__ bgn)
{
    __shared__ float scomb[NB][KH];
    __shared__ float sgi[NB][G];
    __shared__ float sh[NB][G];
    __shared__ float srh[NB][G];

    const int g  = threadIdx.x;
    const int b0 = blockIdx.x * NB;

    for (int i = g; i < NB*KH; i += G) {
        int bb = i / KH, ii = i - bb*KH;
        scomb[bb][ii] = g_comb[(size_t)(b0 + bb)*KH + ii];
    }
    for (int i = g; i < NB*G; i += G) {
        int bb = i >> 8, ii = i & (G-1);
        sh[bb][ii] = g_h[(size_t)(b0 + bb)*G + ii];
    }
    __syncthreads();

    // gi = comb @ Wgp + bgp
    float accg[NB];
    {
        float bv = bgp[g];
        #pragma unroll
        for (int bb = 0; bb < NB; bb++) accg[bb] = bv;
    }
    for (int i = 0; i < KH; i++) {
        float wp = Wgp[i*G + g];
        #pragma unroll
        for (int bb = 0; bb < NB; bb++) accg[bb] += scomb[bb][i] * wp;
    }
    #pragma unroll
    for (int bb = 0; bb < NB; bb++) sgi[bb][g] = accg[bb];
    __syncthreads();

    // pass 1: z, r pre-activations, and gi @ Wgn partial for n
    float az[NB], ar[NB], an[NB];
    {
        float bzv = bgz[g], brv = bgr[g], bnv = bgn[g];
        #pragma unroll
        for (int bb = 0; bb < NB; bb++) { az[bb] = bzv; ar[bb] = brv; an[bb] = bnv; }
    }
    for (int i = 0; i < G; i++) {
        float wz = Wgz[i*G + g], uz = Ugz[i*G + g];
        float wr = Wgr[i*G + g], ur = Ugr[i*G + g];
        float wn = Wgn[i*G + g];
        #pragma unroll
        for (int bb = 0; bb < NB; bb++) {
            float gv = sgi[bb][i], hv = sh[bb][i];
            az[bb] += gv*wz + hv*uz;
            ar[bb] += gv*wr + hv*ur;
            an[bb] += gv*wn;
        }
    }
    float zz[NB];
    #pragma unroll
    for (int bb = 0; bb < NB; bb++) {
        zz[bb]   = 1.f / (1.f + expf(-az[bb]));
        float r  = 1.f / (1.f + expf(-ar[bb]));
        srh[bb][g] = r * sh[bb][g];
    }
    __syncthreads();

    // pass 2: (r*h) @ Ugn
    for (int i = 0; i < G; i++) {
        float un = Ugn[i*G + g];
        #pragma unroll
        for (int bb = 0; bb < NB; bb++) an[bb] += srh[bb][i] * un;
    }
    #pragma unroll
    for (int bb = 0; bb < NB; bb++) {
        float gn = tanhf(an[bb]);
        // h_new = (1 - gz) * gn + gz * h_old   (note: opposite convention vs inner GRU)
        g_h[(size_t)(b0 + bb)*G + g] = (1.f - zz[bb])*gn + zz[bb]*sh[bb][g];
    }
}

// Classifier: one block per batch element, 64 threads (hidden dim).
__global__ __launch_bounds__(64) void cls_kernel(
    const float* __restrict__ W1, const float* __restrict__ b1,
    const float* __restrict__ W2, const float* __restrict__ b2,
    float* __restrict__ out)
{
    __shared__ float wsum[2];
    const int b = blockIdx.x;
    const int j = threadIdx.x;

    const float* hb = g_h + (size_t)b*G;
    float acc = b1[j];
    #pragma unroll 8
    for (int i = 0; i < G; i++) acc += hb[i] * W1[i*64 + j];
    float hid = fmaxf(acc, 0.f);
    float v = hid * W2[j];
    #pragma unroll
    for (int o = 16; o > 0; o >>= 1) v += __shfl_down_sync(0xffffffffu, v, o);
    if ((j & 31) == 0) wsum[j >> 5] = v;
    __syncthreads();
    if (j == 0) {
        float s = wsum[0] + wsum[1] + b2[0];
        out[b] = 1.f / (1.f + expf(-s));
    }
}

extern "C" void kernel_launch(void* const* d_in, const int* in_sizes, int n_in,
                              void* d_out, int out_size)
{
    const float* x    = (const float*)d_in[0];
    const float* adj  = (const float*)d_in[1];
    const float* W_fi = (const float*)d_in[2];
    const float* b_fi = (const float*)d_in[3];
    const float* Wz   = (const float*)d_in[4];
    const float* Uz   = (const float*)d_in[5];
    const float* bz   = (const float*)d_in[6];
    const float* Wr   = (const float*)d_in[7];
    const float* Ur   = (const float*)d_in[8];
    const float* br   = (const float*)d_in[9];
    const float* Wh   = (const float*)d_in[10];
    const float* Uh   = (const float*)d_in[11];
    const float* bh   = (const float*)d_in[12];
    const float* Wgp  = (const float*)d_in[13];
    const float* bgp  = (const float*)d_in[14];
    const float* Wgz  = (const float*)d_in[15];
    const float* Ugz  = (const float*)d_in[16];
    const float* bgz  = (const float*)d_in[17];
    const float* Wgr  = (const float*)d_in[18];
    const float* Ugr  = (const float*)d_in[19];
    const float* bgr  = (const float*)d_in[20];
    const float* Wgn  = (const float*)d_in[21];
    const float* Ugn  = (const float*)d_in[22];
    const float* bgn  = (const float*)d_in[23];
    const float* W1   = (const float*)d_in[24];
    const float* b1   = (const float*)d_in[25];
    const float* W2   = (const float*)d_in[26];
    const float* b2   = (const float*)d_in[27];
    float* out = (float*)d_out;

    zero_h_kernel<<<(B*G + 255)/256, 256>>>();
    for (int t = 0; t < T; t++) {
        gnn_kernel<<<B, KH>>>(t, x, adj, W_fi, b_fi,
                              Wz, Uz, bz, Wr, Ur, br, Wh, Uh, bh);
        garu_kernel<<<B/NB, G>>>(Wgp, bgp, Wgz, Ugz, bgz,
                                 Wgr, Ugr, bgr, Wgn, Ugn, bgn);
    }
    cls_kernel<<<B, 64>>>(W1, b1, W2, b2, out);
}

// round 4
// speedup vs baseline: 2.0430x; 2.0430x over previous
#include <cuda_runtime.h>
#include <math.h>

#define T 96
#define B 1024
#define K 10
#define C 16
#define H 32
#define G 256
#define L 4
#define KH (K*H)     // 320
#define E4 4         // batch elements per GNN block
#define GB 8         // batch elements per GARU block
#define GT 512       // GARU threads (2 halves x 256 columns)

// Scratch: GNN outputs for ALL timesteps, layout [T][KH][B] so GARU loads float4 over batch.
__device__ float g_comb[(size_t)T * KH * B];
__device__ float g_h[B * G];

__device__ __forceinline__ float sigmoidf_(float v) { return 1.f / (1.f + expf(-v)); }

// ---------------------------------------------------------------------------
// GNN: grid (B/E4, T), 320 threads = (k,j). 4 batch elements per block.
// ---------------------------------------------------------------------------
__global__ __launch_bounds__(KH) void gnn_kernel(
    const float* __restrict__ x, const float* __restrict__ adj,
    const float* __restrict__ W_fi, const float* __restrict__ b_fi,
    const float* __restrict__ Wz, const float* __restrict__ Uz, const float* __restrict__ bz,
    const float* __restrict__ Wr, const float* __restrict__ Ur, const float* __restrict__ br,
    const float* __restrict__ Wh, const float* __restrict__ Uh, const float* __restrict__ bh)
{
    __shared__ float  sx[E4][K*C];
    __shared__ float  sadj[E4][K*K];
    __shared__ float  sdeg[E4][K];
    __shared__ float4 sh4[KH];     // h,  component e = batch element
    __shared__ float4 sh04[KH];    // h0
    __shared__ float4 sm4[KH];     // m
    __shared__ float4 srh4[KH];    // r*h

    const int b0  = blockIdx.x * E4;
    const int t   = blockIdx.y;
    const int tid = threadIdx.x;
    const int k   = tid >> 5;
    const int j   = tid & 31;

    for (int idx = tid; idx < E4*K*C; idx += KH) {
        int e = idx / (K*C), r = idx - e*(K*C);
        sx[e][r] = x[((size_t)t*B + b0 + e)*(K*C) + r];
    }
    for (int idx = tid; idx < E4*K*K; idx += KH) {
        int e = idx / (K*K), r = idx - e*(K*K);
        int row = r / K, col = r - row*K;
        sadj[e][r] = adj[((size_t)t*B + b0 + e)*(K*K) + r] + (row == col ? 1.f : 0.f);
    }
    __syncthreads();
    if (tid < E4*K) {
        int e = tid / K, r = tid - e*K;
        float s = 0.f;
        #pragma unroll
        for (int i = 0; i < K; i++) s += sadj[e][r*K + i];
        sdeg[e][r] = 1.f / (s + 1e-6f);
    }
    __syncthreads();
    for (int idx = tid; idx < E4*K*K; idx += KH) {
        int e = idx / (K*K), r = idx - e*(K*K);
        sadj[e][r] *= sdeg[e][r / K];
    }

    // h0 = x @ W_fi + b_fi  (weight loaded once, used for 4 elements)
    float a0[E4];
    {
        float bv = b_fi[j];
        #pragma unroll
        for (int e = 0; e < E4; e++) a0[e] = bv;
    }
    #pragma unroll
    for (int c = 0; c < C; c++) {
        float w = W_fi[c*H + j];
        #pragma unroll
        for (int e = 0; e < E4; e++) a0[e] += sx[e][k*C + c] * w;
    }
    {
        float4 v = make_float4(a0[0], a0[1], a0[2], a0[3]);
        sh04[tid] = v;
        sh4[tid]  = v;
    }
    __syncthreads();

    for (int l = 0; l < L; l++) {
        const float* Wzl = Wz + l*H*H; const float* Uzl = Uz + l*H*H;
        const float* Wrl = Wr + l*H*H; const float* Url = Ur + l*H*H;
        const float* Whl = Wh + l*H*H; const float* Uhl = Uh + l*H*H;

        // m = adj_norm @ h
        float m[E4] = {0.f, 0.f, 0.f, 0.f};
        #pragma unroll
        for (int i = 0; i < K; i++) {
            float4 hv = sh4[i*H + j];
            m[0] += sadj[0][k*K + i] * hv.x;
            m[1] += sadj[1][k*K + i] * hv.y;
            m[2] += sadj[2][k*K + i] * hv.z;
            m[3] += sadj[3][k*K + i] * hv.w;
        }
        sm4[tid] = make_float4(m[0], m[1], m[2], m[3]);
        __syncthreads();

        // z, r gates
        float az[E4], ar[E4];
        {
            float bzv = bz[l*H + j], brv = br[l*H + j];
            #pragma unroll
            for (int e = 0; e < E4; e++) { az[e] = bzv; ar[e] = brv; }
        }
        #pragma unroll 4
        for (int i = 0; i < H; i++) {
            float wz = Wzl[i*H + j], uz = Uzl[i*H + j];
            float wr = Wrl[i*H + j], ur = Url[i*H + j];
            float4 mv = sm4[k*H + i];
            float4 hv = sh4[k*H + i];
            az[0] += mv.x*wz + hv.x*uz;  ar[0] += mv.x*wr + hv.x*ur;
            az[1] += mv.y*wz + hv.y*uz;  ar[1] += mv.y*wr + hv.y*ur;
            az[2] += mv.z*wz + hv.z*uz;  ar[2] += mv.z*wr + hv.z*ur;
            az[3] += mv.w*wz + hv.w*uz;  ar[3] += mv.w*wr + hv.w*ur;
        }
        float zg[E4], rg[E4];
        #pragma unroll
        for (int e = 0; e < E4; e++) {
            zg[e] = sigmoidf_(az[e]);
            rg[e] = sigmoidf_(ar[e]);
        }
        float4 hown = sh4[tid];
        srh4[tid] = make_float4(rg[0]*hown.x, rg[1]*hown.y, rg[2]*hown.z, rg[3]*hown.w);
        __syncthreads();

        // n gate
        float an[E4];
        {
            float bnv = bh[l*H + j];
            #pragma unroll
            for (int e = 0; e < E4; e++) an[e] = bnv;
        }
        #pragma unroll 4
        for (int i = 0; i < H; i++) {
            float wh = Whl[i*H + j], uh = Uhl[i*H + j];
            float4 mv = sm4[k*H + i];
            float4 rv = srh4[k*H + i];
            an[0] += mv.x*wh + rv.x*uh;
            an[1] += mv.y*wh + rv.y*uh;
            an[2] += mv.z*wh + rv.z*uh;
            an[3] += mv.w*wh + rv.w*uh;
        }
        float4 h0v = sh04[tid];
        float4 hn;
        hn.x = (1.f - zg[0])*hown.x + zg[0]*tanhf(an[0]) + h0v.x;
        hn.y = (1.f - zg[1])*hown.y + zg[1]*tanhf(an[1]) + h0v.y;
        hn.z = (1.f - zg[2])*hown.z + zg[2]*tanhf(an[2]) + h0v.z;
        hn.w = (1.f - zg[3])*hown.w + zg[3]*tanhf(an[3]) + h0v.w;
        sh4[tid] = hn;   // safe: all sh4 reads of this layer completed before srh sync
        __syncthreads();
    }

    // Store comb, layout [t][kh][b]: 4 consecutive batch floats -> one STG.128
    *(float4*)&g_comb[((size_t)t*KH + tid)*B + b0] = sh4[tid];
}

// ---------------------------------------------------------------------------
// GARU: persistent over all T. 128 blocks x 512 threads.
// tid = hf*256 + g; half hf owns batch group float4 [4*hf .. 4*hf+3].
// h lives in smem for all 96 steps.
// ---------------------------------------------------------------------------
__global__ __launch_bounds__(GT) void garu_kernel(
    const float* __restrict__ Wgp, const float* __restrict__ bgp,
    const float* __restrict__ Wgz, const float* __restrict__ Ugz, const float* __restrict__ bgz,
    const float* __restrict__ Wgr, const float* __restrict__ Ugr, const float* __restrict__ bgr,
    const float* __restrict__ Wgn, const float* __restrict__ Ugn, const float* __restrict__ bgn)
{
    __shared__ float4 scomb4[KH][2];
    __shared__ float4 sgi4[G][2];
    __shared__ float4 sh4[G][2];
    __shared__ float4 srh4[G][2];

    const int tid = threadIdx.x;
    const int g   = tid & (G - 1);
    const int hf  = tid >> 8;
    const int b0  = blockIdx.x * GB;

    sh4[g][hf] = make_float4(0.f, 0.f, 0.f, 0.f);
    __syncthreads();

    const float bgpv = bgp[g], bgzv = bgz[g], bgrv = bgr[g], bgnv = bgn[g];

    for (int t = 0; t < T; t++) {
        // stage comb tile for this block's 8 batches
        for (int idx = tid; idx < KH*2; idx += GT) {
            int i = idx >> 1, w = idx & 1;
            scomb4[i][w] = *(const float4*)&g_comb[((size_t)t*KH + i)*B + b0 + 4*w];
        }
        __syncthreads();   // also publishes last step's sh4 update

        // gi = comb @ Wgp + bgp
        float ag[4] = {bgpv, bgpv, bgpv, bgpv};
        #pragma unroll 4
        for (int i = 0; i < KH; i++) {
            float wp = Wgp[i*G + g];
            float4 cv = scomb4[i][hf];
            ag[0] += cv.x*wp; ag[1] += cv.y*wp; ag[2] += cv.z*wp; ag[3] += cv.w*wp;
        }
        sgi4[g][hf] = make_float4(ag[0], ag[1], ag[2], ag[3]);
        __syncthreads();

        // pass 1: z, r pre-activations + gi @ Wgn
        float az[4] = {bgzv, bgzv, bgzv, bgzv};
        float ar[4] = {bgrv, bgrv, bgrv, bgrv};
        float an[4] = {bgnv, bgnv, bgnv, bgnv};
        #pragma unroll 2
        for (int i = 0; i < G; i++) {
            float wz = Wgz[i*G + g], uz = Ugz[i*G + g];
            float wr = Wgr[i*G + g], ur = Ugr[i*G + g];
            float wn = Wgn[i*G + g];
            float4 gv = sgi4[i][hf];
            float4 hv = sh4[i][hf];
            az[0] += gv.x*wz + hv.x*uz;  ar[0] += gv.x*wr + hv.x*ur;  an[0] += gv.x*wn;
            az[1] += gv.y*wz + hv.y*uz;  ar[1] += gv.y*wr + hv.y*ur;  an[1] += gv.y*wn;
            az[2] += gv.z*wz + hv.z*uz;  ar[2] += gv.z*wr + hv.z*ur;  an[2] += gv.z*wn;
            az[3] += gv.w*wz + hv.w*uz;  ar[3] += gv.w*wr + hv.w*ur;  an[3] += gv.w*wn;
        }
        float4 hown = sh4[g][hf];
        float zz[4];
        zz[0] = sigmoidf_(az[0]); zz[1] = sigmoidf_(az[1]);
        zz[2] = sigmoidf_(az[2]); zz[3] = sigmoidf_(az[3]);
        {
            float r0 = sigmoidf_(ar[0]), r1 = sigmoidf_(ar[1]);
            float r2 = sigmoidf_(ar[2]), r3 = sigmoidf_(ar[3]);
            srh4[g][hf] = make_float4(r0*hown.x, r1*hown.y, r2*hown.z, r3*hown.w);
        }
        __syncthreads();

        // pass 2: (r*h) @ Ugn
        #pragma unroll 4
        for (int i = 0; i < G; i++) {
            float un = Ugn[i*G + g];
            float4 sv = srh4[i][hf];
            an[0] += sv.x*un; an[1] += sv.y*un; an[2] += sv.z*un; an[3] += sv.w*un;
        }
        float4 hn;
        hn.x = (1.f - zz[0])*tanhf(an[0]) + zz[0]*hown.x;
        hn.y = (1.f - zz[1])*tanhf(an[1]) + zz[1]*hown.y;
        hn.z = (1.f - zz[2])*tanhf(an[2]) + zz[2]*hown.z;
        hn.w = (1.f - zz[3])*tanhf(an[3]) + zz[3]*hown.w;
        sh4[g][hf] = hn;   // safe: no thread reads sh4 after the srh sync within this step
    }

    // final hidden -> global (for classifier)
    float4 hv = sh4[g][hf];
    g_h[(size_t)(b0 + 4*hf + 0)*G + g] = hv.x;
    g_h[(size_t)(b0 + 4*hf + 1)*G + g] = hv.y;
    g_h[(size_t)(b0 + 4*hf + 2)*G + g] = hv.z;
    g_h[(size_t)(b0 + 4*hf + 3)*G + g] = hv.w;
}

// ---------------------------------------------------------------------------
// Classifier: one block per batch element, 64 threads (hidden dim).
// ---------------------------------------------------------------------------
__global__ __launch_bounds__(64) void cls_kernel(
    const float* __restrict__ W1, const float* __restrict__ b1,
    const float* __restrict__ W2, const float* __restrict__ b2,
    float* __restrict__ out)
{
    __shared__ float wsum[2];
    const int b = blockIdx.x;
    const int j = threadIdx.x;

    const float* hb = g_h + (size_t)b*G;
    float acc = b1[j];
    #pragma unroll 8
    for (int i = 0; i < G; i++) acc += hb[i] * W1[i*64 + j];
    float hid = fmaxf(acc, 0.f);
    float v = hid * W2[j];
    #pragma unroll
    for (int o = 16; o > 0; o >>= 1) v += __shfl_down_sync(0xffffffffu, v, o);
    if ((j & 31) == 0) wsum[j >> 5] = v;
    __syncthreads();
    if (j == 0) {
        float s = wsum[0] + wsum[1] + b2[0];
        out[b] = 1.f / (1.f + expf(-s));
    }
}

extern "C" void kernel_launch(void* const* d_in, const int* in_sizes, int n_in,
                              void* d_out, int out_size)
{
    const float* x    = (const float*)d_in[0];
    const float* adj  = (const float*)d_in[1];
    const float* W_fi = (const float*)d_in[2];
    const float* b_fi = (const float*)d_in[3];
    const float* Wz   = (const float*)d_in[4];
    const float* Uz   = (const float*)d_in[5];
    const float* bz   = (const float*)d_in[6];
    const float* Wr   = (const float*)d_in[7];
    const float* Ur   = (const float*)d_in[8];
    const float* br   = (const float*)d_in[9];
    const float* Wh   = (const float*)d_in[10];
    const float* Uh   = (const float*)d_in[11];
    const float* bh   = (const float*)d_in[12];
    const float* Wgp  = (const float*)d_in[13];
    const float* bgp  = (const float*)d_in[14];
    const float* Wgz  = (const float*)d_in[15];
    const float* Ugz  = (const float*)d_in[16];
    const float* bgz  = (const float*)d_in[17];
    const float* Wgr  = (const float*)d_in[18];
    const float* Ugr  = (const float*)d_in[19];
    const float* bgr  = (const float*)d_in[20];
    const float* Wgn  = (const float*)d_in[21];
    const float* Ugn  = (const float*)d_in[22];
    const float* bgn  = (const float*)d_in[23];
    const float* W1   = (const float*)d_in[24];
    const float* b1   = (const float*)d_in[25];
    const float* W2   = (const float*)d_in[26];
    const float* b2   = (const float*)d_in[27];
    float* out = (float*)d_out;

    // Phase 1: all GNN steps in one launch (no temporal dependence).
    gnn_kernel<<<dim3(B/E4, T), KH>>>(x, adj, W_fi, b_fi,
                                      Wz, Uz, bz, Wr, Ur, br, Wh, Uh, bh);
    // Phase 2: persistent GARU over all timesteps (per-batch recurrence only).
    garu_kernel<<<B/GB, GT>>>(Wgp, bgp, Wgz, Ugz, bgz,
                              Wgr, Ugr, bgr, Wgn, Ugn, bgn);
    // Phase 3: classifier.
    cls_kernel<<<B, 64>>>(W1, b1, W2, b2, out);
}

// round 5
// speedup vs baseline: 3.1674x; 1.5504x over previous
#include <cuda_runtime.h>
#include <math.h>

#define T 96
#define B 1024
#define K 10
#define C 16
#define H 32
#define G 256
#define L 4
#define KH (K*H)     // 320
#define E4 4         // batch elements per GNN block
#define GB 8         // batch elements per GARU block
#define GT 512       // GARU threads (256 columns x 2 reduction halves)

// Scratch: GNN outputs for ALL timesteps, layout [T][KH][B] so GARU loads float4 over batch.
__device__ float g_comb[(size_t)T * KH * B];
__device__ float g_h[B * G];

__device__ __forceinline__ float fast_tanh(float x) {
    float y;
    asm("tanh.approx.f32 %0, %1;" : "=f"(y) : "f"(x));
    return y;
}
__device__ __forceinline__ float fast_sigmoid(float x) {
    // sigmoid(x) == 0.5*tanh(0.5x) + 0.5 (exact identity)
    return fmaf(0.5f, fast_tanh(0.5f * x), 0.5f);
}
__device__ __forceinline__ float4 f4add(float4 a, float4 b) {
    return make_float4(a.x + b.x, a.y + b.y, a.z + b.z, a.w + b.w);
}

// ---------------------------------------------------------------------------
// GNN: grid (B/E4, T), 320 threads = (k,j). 4 batch elements per block.
// ---------------------------------------------------------------------------
__global__ __launch_bounds__(KH) void gnn_kernel(
    const float* __restrict__ x, const float* __restrict__ adj,
    const float* __restrict__ W_fi, const float* __restrict__ b_fi,
    const float* __restrict__ Wz, const float* __restrict__ Uz, const float* __restrict__ bz,
    const float* __restrict__ Wr, const float* __restrict__ Ur, const float* __restrict__ br,
    const float* __restrict__ Wh, const float* __restrict__ Uh, const float* __restrict__ bh)
{
    __shared__ float  sx[E4][K*C];
    __shared__ float  sadj[E4][K*K];
    __shared__ float  sdeg[E4][K];
    __shared__ float4 sh4[KH];     // h  (component e = batch element)
    __shared__ float4 sh04[KH];    // h0
    __shared__ float4 sm4[KH];     // m
    __shared__ float4 srh4[KH];    // r*h

    const int b0  = blockIdx.x * E4;
    const int t   = blockIdx.y;
    const int tid = threadIdx.x;
    const int k   = tid >> 5;
    const int j   = tid & 31;

    for (int idx = tid; idx < E4*K*C; idx += KH) {
        int e = idx / (K*C), r = idx - e*(K*C);
        sx[e][r] = x[((size_t)t*B + b0 + e)*(K*C) + r];
    }
    for (int idx = tid; idx < E4*K*K; idx += KH) {
        int e = idx / (K*K), r = idx - e*(K*K);
        int row = r / K, col = r - row*K;
        sadj[e][r] = adj[((size_t)t*B + b0 + e)*(K*K) + r] + (row == col ? 1.f : 0.f);
    }
    __syncthreads();
    if (tid < E4*K) {
        int e = tid / K, r = tid - e*K;
        float s = 0.f;
        #pragma unroll
        for (int i = 0; i < K; i++) s += sadj[e][r*K + i];
        sdeg[e][r] = 1.f / (s + 1e-6f);
    }
    __syncthreads();
    for (int idx = tid; idx < E4*K*K; idx += KH) {
        int e = idx / (K*K), r = idx - e*(K*K);
        sadj[e][r] *= sdeg[e][r / K];
    }

    // h0 = x @ W_fi + b_fi
    float a0[E4];
    {
        float bv = b_fi[j];
        #pragma unroll
        for (int e = 0; e < E4; e++) a0[e] = bv;
    }
    #pragma unroll
    for (int c = 0; c < C; c++) {
        float w = W_fi[c*H + j];
        #pragma unroll
        for (int e = 0; e < E4; e++) a0[e] += sx[e][k*C + c] * w;
    }
    {
        float4 v = make_float4(a0[0], a0[1], a0[2], a0[3]);
        sh04[tid] = v;
        sh4[tid]  = v;
    }
    __syncthreads();

    for (int l = 0; l < L; l++) {
        const float* Wzl = Wz + l*H*H; const float* Uzl = Uz + l*H*H;
        const float* Wrl = Wr + l*H*H; const float* Url = Ur + l*H*H;
        const float* Whl = Wh + l*H*H; const float* Uhl = Uh + l*H*H;

        // m = adj_norm @ h
        float m[E4] = {0.f, 0.f, 0.f, 0.f};
        #pragma unroll
        for (int i = 0; i < K; i++) {
            float4 hv = sh4[i*H + j];
            m[0] += sadj[0][k*K + i] * hv.x;
            m[1] += sadj[1][k*K + i] * hv.y;
            m[2] += sadj[2][k*K + i] * hv.z;
            m[3] += sadj[3][k*K + i] * hv.w;
        }
        sm4[tid] = make_float4(m[0], m[1], m[2], m[3]);
        __syncthreads();

        // fused z, r gates + m @ Wh partial of n
        float az[E4], ar[E4], an[E4];
        {
            float bzv = bz[l*H + j], brv = br[l*H + j], bnv = bh[l*H + j];
            #pragma unroll
            for (int e = 0; e < E4; e++) { az[e] = bzv; ar[e] = brv; an[e] = bnv; }
        }
        #pragma unroll 4
        for (int i = 0; i < H; i++) {
            float wz = Wzl[i*H + j], uz = Uzl[i*H + j];
            float wr = Wrl[i*H + j], ur = Url[i*H + j];
            float wh = Whl[i*H + j];
            float4 mv = sm4[k*H + i];
            float4 hv = sh4[k*H + i];
            az[0] += mv.x*wz + hv.x*uz;  ar[0] += mv.x*wr + hv.x*ur;  an[0] += mv.x*wh;
            az[1] += mv.y*wz + hv.y*uz;  ar[1] += mv.y*wr + hv.y*ur;  an[1] += mv.y*wh;
            az[2] += mv.z*wz + hv.z*uz;  ar[2] += mv.z*wr + hv.z*ur;  an[2] += mv.z*wh;
            az[3] += mv.w*wz + hv.w*uz;  ar[3] += mv.w*wr + hv.w*ur;  an[3] += mv.w*wh;
        }
        float zg[E4], rg[E4];
        #pragma unroll
        for (int e = 0; e < E4; e++) {
            zg[e] = fast_sigmoid(az[e]);
            rg[e] = fast_sigmoid(ar[e]);
        }
        float4 hown = sh4[tid];
        srh4[tid] = make_float4(rg[0]*hown.x, rg[1]*hown.y, rg[2]*hown.z, rg[3]*hown.w);
        __syncthreads();

        // n gate remainder: (r*h) @ Uh
        #pragma unroll 4
        for (int i = 0; i < H; i++) {
            float uh = Uhl[i*H + j];
            float4 rv = srh4[k*H + i];
            an[0] += rv.x*uh;
            an[1] += rv.y*uh;
            an[2] += rv.z*uh;
            an[3] += rv.w*uh;
        }
        float4 h0v = sh04[tid];
        float4 hn;
        hn.x = (1.f - zg[0])*hown.x + zg[0]*fast_tanh(an[0]) + h0v.x;
        hn.y = (1.f - zg[1])*hown.y + zg[1]*fast_tanh(an[1]) + h0v.y;
        hn.z = (1.f - zg[2])*hown.z + zg[2]*fast_tanh(an[2]) + h0v.z;
        hn.w = (1.f - zg[3])*hown.w + zg[3]*fast_tanh(an[3]) + h0v.w;
        __syncthreads();
        sh4[tid] = hn;
        __syncthreads();
    }

    // Store comb, layout [t][kh][b]
    *(float4*)&g_comb[((size_t)t*KH + tid)*B + b0] = sh4[tid];
}

// ---------------------------------------------------------------------------
// GARU: persistent over all T. 128 blocks x 512 threads.
// tid = half*256 + g. Each thread accumulates ALL 8 batches over HALF of the
// reduction dimension; halves combine via smem. h lives in smem across steps.
// Dynamic smem layout (float4 units):
//   scomb4 [KH][2] | sgi4 [G][2] | sh4 [G][2] | srh4 [G][2] | sred [6][GT]
// ---------------------------------------------------------------------------
__global__ __launch_bounds__(GT, 1) void garu_kernel(
    const float* __restrict__ Wgp, const float* __restrict__ bgp,
    const float* __restrict__ Wgz, const float* __restrict__ Ugz, const float* __restrict__ bgz,
    const float* __restrict__ Wgr, const float* __restrict__ Ugr, const float* __restrict__ bgr,
    const float* __restrict__ Wgn, const float* __restrict__ Ugn, const float* __restrict__ bgn)
{
    extern __shared__ float4 dyn[];
    float4* scomb4 = dyn;                 // [KH*2], idx i*2+w
    float4* sgi4   = scomb4 + KH*2;       // [G*2]
    float4* sh4    = sgi4   + G*2;        // [G*2]
    float4* srh4   = sh4    + G*2;        // [G*2]
    float4* sred   = srh4   + G*2;        // [6*GT], slot s at sred + s*GT

    const int tid  = threadIdx.x;
    const int g    = tid & (G - 1);
    const int half = tid >> 8;
    const int b0   = blockIdx.x * GB;

    sh4[g*2 + half] = make_float4(0.f, 0.f, 0.f, 0.f);

    const float bgpv = bgp[g], bgzv = bgz[g], bgrv = bgr[g], bgnv = bgn[g];
    const float4 bgp4 = make_float4(bgpv, bgpv, bgpv, bgpv);

    for (int t = 0; t < T; t++) {
        // stage comb tile for this block's 8 batches (also fences last step's sh4)
        for (int idx = tid; idx < KH*2; idx += GT) {
            scomb4[idx] = *(const float4*)&g_comb[((size_t)t*KH + (idx >> 1))*B + b0 + 4*(idx & 1)];
        }
        __syncthreads();

        // gi = comb @ Wgp + bgp  -- split-K: half covers 160 of 320 rows, all 8 batches
        float ag[8] = {0,0,0,0,0,0,0,0};
        {
            const int i0 = half * (KH/2);
            #pragma unroll 4
            for (int i = i0; i < i0 + KH/2; i++) {
                float wp = Wgp[i*G + g];
                float4 c0 = scomb4[i*2 + 0];
                float4 c1 = scomb4[i*2 + 1];
                ag[0] += c0.x*wp; ag[1] += c0.y*wp; ag[2] += c0.z*wp; ag[3] += c0.w*wp;
                ag[4] += c1.x*wp; ag[5] += c1.y*wp; ag[6] += c1.z*wp; ag[7] += c1.w*wp;
            }
        }
        sred[0*GT + tid] = make_float4(ag[0], ag[1], ag[2], ag[3]);
        sred[1*GT + tid] = make_float4(ag[4], ag[5], ag[6], ag[7]);
        __syncthreads();
        // combine: thread (g,half) owns batch-group `half`
        sgi4[g*2 + half] = f4add(f4add(sred[half*GT + g], sred[half*GT + 256 + g]), bgp4);
        __syncthreads();

        // pass 1 (split-K over 128 of 256): z, r pre-acts + gi @ Wgn, all 8 batches
        float az[8] = {0,0,0,0,0,0,0,0};
        float ar[8] = {0,0,0,0,0,0,0,0};
        float an[8] = {0,0,0,0,0,0,0,0};
        {
            const int i0 = half * (G/2);
            #pragma unroll 2
            for (int i = i0; i < i0 + G/2; i++) {
                float wz = Wgz[i*G + g], uz = Ugz[i*G + g];
                float wr = Wgr[i*G + g], ur = Ugr[i*G + g];
                float wn = Wgn[i*G + g];
                float4 g0 = sgi4[i*2 + 0];
                float4 g1 = sgi4[i*2 + 1];
                float4 h0 = sh4[i*2 + 0];
                float4 h1 = sh4[i*2 + 1];
                az[0] += g0.x*wz + h0.x*uz;  ar[0] += g0.x*wr + h0.x*ur;  an[0] += g0.x*wn;
                az[1] += g0.y*wz + h0.y*uz;  ar[1] += g0.y*wr + h0.y*ur;  an[1] += g0.y*wn;
                az[2] += g0.z*wz + h0.z*uz;  ar[2] += g0.z*wr + h0.z*ur;  an[2] += g0.z*wn;
                az[3] += g0.w*wz + h0.w*uz;  ar[3] += g0.w*wr + h0.w*ur;  an[3] += g0.w*wn;
                az[4] += g1.x*wz + h1.x*uz;  ar[4] += g1.x*wr + h1.x*ur;  an[4] += g1.x*wn;
                az[5] += g1.y*wz + h1.y*uz;  ar[5] += g1.y*wr + h1.y*ur;  an[5] += g1.y*wn;
                az[6] += g1.z*wz + h1.z*uz;  ar[6] += g1.z*wr + h1.z*ur;  an[6] += g1.z*wn;
                az[7] += g1.w*wz + h1.w*uz;  ar[7] += g1.w*wr + h1.w*ur;  an[7] += g1.w*wn;
            }
        }
        sred[0*GT + tid] = make_float4(az[0], az[1], az[2], az[3]);
        sred[1*GT + tid] = make_float4(az[4], az[5], az[6], az[7]);
        sred[2*GT + tid] = make_float4(ar[0], ar[1], ar[2], ar[3]);
        sred[3*GT + tid] = make_float4(ar[4], ar[5], ar[6], ar[7]);
        sred[4*GT + tid] = make_float4(an[0], an[1], an[2], an[3]);
        sred[5*GT + tid] = make_float4(an[4], an[5], an[6], an[7]);
        __syncthreads();

        float4 az4 = f4add(sred[(0+half)*GT + g], sred[(0+half)*GT + 256 + g]);
        float4 ar4 = f4add(sred[(2+half)*GT + g], sred[(2+half)*GT + 256 + g]);
        float4 anp = f4add(sred[(4+half)*GT + g], sred[(4+half)*GT + 256 + g]);
        float4 hown = sh4[g*2 + half];
        float4 zz;
        zz.x = fast_sigmoid(az4.x + bgzv);  zz.y = fast_sigmoid(az4.y + bgzv);
        zz.z = fast_sigmoid(az4.z + bgzv);  zz.w = fast_sigmoid(az4.w + bgzv);
        {
            float r0 = fast_sigmoid(ar4.x + bgrv), r1 = fast_sigmoid(ar4.y + bgrv);
            float r2 = fast_sigmoid(ar4.z + bgrv), r3 = fast_sigmoid(ar4.w + bgrv);
            srh4[g*2 + half] = make_float4(r0*hown.x, r1*hown.y, r2*hown.z, r3*hown.w);
        }
        float4 antot = make_float4(anp.x + bgnv, anp.y + bgnv, anp.z + bgnv, anp.w + bgnv);
        __syncthreads();

        // pass 2 (split-K): (r*h) @ Ugn, all 8 batches
        float a2[8] = {0,0,0,0,0,0,0,0};
        {
            const int i0 = half * (G/2);
            #pragma unroll 4
            for (int i = i0; i < i0 + G/2; i++) {
                float un = Ugn[i*G + g];
                float4 s0 = srh4[i*2 + 0];
                float4 s1 = srh4[i*2 + 1];
                a2[0] += s0.x*un; a2[1] += s0.y*un; a2[2] += s0.z*un; a2[3] += s0.w*un;
                a2[4] += s1.x*un; a2[5] += s1.y*un; a2[6] += s1.z*un; a2[7] += s1.w*un;
            }
        }
        sred[0*GT + tid] = make_float4(a2[0], a2[1], a2[2], a2[3]);
        sred[1*GT + tid] = make_float4(a2[4], a2[5], a2[6], a2[7]);
        __syncthreads();
        {
            float4 p = f4add(sred[half*GT + g], sred[half*GT + 256 + g]);
            float4 hn;
            hn.x = (1.f - zz.x)*fast_tanh(antot.x + p.x) + zz.x*hown.x;
            hn.y = (1.f - zz.y)*fast_tanh(antot.y + p.y) + zz.y*hown.y;
            hn.z = (1.f - zz.z)*fast_tanh(antot.z + p.z) + zz.z*hown.z;
            hn.w = (1.f - zz.w)*fast_tanh(antot.w + p.w) + zz.w*hown.w;
            sh4[g*2 + half] = hn;   // fenced by next step's top barrier
        }
    }

    __syncthreads();
    // final hidden -> global (for classifier)
    float4 hv = sh4[g*2 + half];
    g_h[(size_t)(b0 + 4*half + 0)*G + g] = hv.x;
    g_h[(size_t)(b0 + 4*half + 1)*G + g] = hv.y;
    g_h[(size_t)(b0 + 4*half + 2)*G + g] = hv.z;
    g_h[(size_t)(b0 + 4*half + 3)*G + g] = hv.w;
}

// ---------------------------------------------------------------------------
// Classifier: one block per batch element, 64 threads (hidden dim).
// ---------------------------------------------------------------------------
__global__ __launch_bounds__(64) void cls_kernel(
    const float* __restrict__ W1, const float* __restrict__ b1,
    const float* __restrict__ W2, const float* __restrict__ b2,
    float* __restrict__ out)
{
    __shared__ float wsum[2];
    const int b = blockIdx.x;
    const int j = threadIdx.x;

    const float* hb = g_h + (size_t)b*G;
    float acc = b1[j];
    #pragma unroll 8
    for (int i = 0; i < G; i++) acc += hb[i] * W1[i*64 + j];
    float hid = fmaxf(acc, 0.f);
    float v = hid * W2[j];
    #pragma unroll
    for (int o = 16; o > 0; o >>= 1) v += __shfl_down_sync(0xffffffffu, v, o);
    if ((j & 31) == 0) wsum[j >> 5] = v;
    __syncthreads();
    if (j == 0) {
        float s = wsum[0] + wsum[1] + b2[0];
        out[b] = fast_sigmoid(s);
    }
}

extern "C" void kernel_launch(void* const* d_in, const int* in_sizes, int n_in,
                              void* d_out, int out_size)
{
    const float* x    = (const float*)d_in[0];
    const float* adj  = (const float*)d_in[1];
    const float* W_fi = (const float*)d_in[2];
    const float* b_fi = (const float*)d_in[3];
    const float* Wz   = (const float*)d_in[4];
    const float* Uz   = (const float*)d_in[5];
    const float* bz   = (const float*)d_in[6];
    const float* Wr   = (const float*)d_in[7];
    const float* Ur   = (const float*)d_in[8];
    const float* br   = (const float*)d_in[9];
    const float* Wh   = (const float*)d_in[10];
    const float* Uh   = (const float*)d_in[11];
    const float* bh   = (const float*)d_in[12];
    const float* Wgp  = (const float*)d_in[13];
    const float* bgp  = (const float*)d_in[14];
    const float* Wgz  = (const float*)d_in[15];
    const float* Ugz  = (const float*)d_in[16];
    const float* bgz  = (const float*)d_in[17];
    const float* Wgr  = (const float*)d_in[18];
    const float* Ugr  = (const float*)d_in[19];
    const float* bgr  = (const float*)d_in[20];
    const float* Wgn  = (const float*)d_in[21];
    const float* Ugn  = (const float*)d_in[22];
    const float* bgn  = (const float*)d_in[23];
    const float* W1   = (const float*)d_in[24];
    const float* b1   = (const float*)d_in[25];
    const float* W2   = (const float*)d_in[26];
    const float* b2   = (const float*)d_in[27];
    float* out = (float*)d_out;

    // GARU dynamic smem: scomb(640) + 3*(512) + sred(3072) float4s = 83,968 B
    const int garu_smem = (KH*2 + G*2*3 + 6*GT) * (int)sizeof(float4);
    static int attr_done = 0;
    if (!attr_done) {
        cudaFuncSetAttribute(garu_kernel,
                             cudaFuncAttributeMaxDynamicSharedMemorySize, garu_smem);
        attr_done = 1;
    }

    gnn_kernel<<<dim3(B/E4, T), KH>>>(x, adj, W_fi, b_fi,
                                      Wz, Uz, bz, Wr, Ur, br, Wh, Uh, bh);
    garu_kernel<<<B/GB, GT, garu_smem>>>(Wgp, bgp, Wgz, Ugz, bgz,
                                         Wgr, Ugr, bgr, Wgn, Ugn, bgn);
    cls_kernel<<<B, 64>>>(W1, b1, W2, b2, out);
}

// round 6
// speedup vs baseline: 3.2765x; 1.0344x over previous
#include <cuda_runtime.h>
#include <math.h>

#define T 96
#define B 1024
#define K 10
#define C 16
#define H 32
#define G 256
#define L 4
#define KH (K*H)     // 320
#define E4 4         // batch elements per GNN block
#define GB 8         // batch elements per GARU block
#define GT 512       // GARU threads (256 columns x 2 reduction halves)

// Scratch: GNN outputs for ALL timesteps, layout [T][KH][B] so GARU loads float4 over batch.
__device__ float g_comb[(size_t)T * KH * B];
__device__ float g_h[B * G];

__device__ __forceinline__ float fast_tanh(float x) {
    float y;
    asm("tanh.approx.f32 %0, %1;" : "=f"(y) : "f"(x));
    return y;
}
__device__ __forceinline__ float fast_sigmoid(float x) {
    // sigmoid(x) == 0.5*tanh(0.5x) + 0.5 (exact identity)
    return fmaf(0.5f, fast_tanh(0.5f * x), 0.5f);
}
__device__ __forceinline__ float4 f4add(float4 a, float4 b) {
    return make_float4(a.x + b.x, a.y + b.y, a.z + b.z, a.w + b.w);
}

// ---------------------------------------------------------------------------
// GNN: grid (B/E4, T), 320 threads = (k,j). 4 batch elements per block.
// ---------------------------------------------------------------------------
__global__ __launch_bounds__(KH) void gnn_kernel(
    const float* __restrict__ x, const float* __restrict__ adj,
    const float* __restrict__ W_fi, const float* __restrict__ b_fi,
    const float* __restrict__ Wz, const float* __restrict__ Uz, const float* __restrict__ bz,
    const float* __restrict__ Wr, const float* __restrict__ Ur, const float* __restrict__ br,
    const float* __restrict__ Wh, const float* __restrict__ Uh, const float* __restrict__ bh)
{
    __shared__ float  sx[E4][K*C];
    __shared__ float  sadj[E4][K*K];
    __shared__ float  sdeg[E4][K];
    __shared__ float4 sh4[KH];     // h  (component e = batch element)
    __shared__ float4 sh04[KH];    // h0
    __shared__ float4 sm4[KH];     // m
    __shared__ float4 srh4[KH];    // r*h

    const int b0  = blockIdx.x * E4;
    const int t   = blockIdx.y;
    const int tid = threadIdx.x;
    const int k   = tid >> 5;
    const int j   = tid & 31;

    for (int idx = tid; idx < E4*K*C; idx += KH) {
        int e = idx / (K*C), r = idx - e*(K*C);
        sx[e][r] = x[((size_t)t*B + b0 + e)*(K*C) + r];
    }
    for (int idx = tid; idx < E4*K*K; idx += KH) {
        int e = idx / (K*K), r = idx - e*(K*K);
        int row = r / K, col = r - row*K;
        sadj[e][r] = adj[((size_t)t*B + b0 + e)*(K*K) + r] + (row == col ? 1.f : 0.f);
    }
    __syncthreads();
    if (tid < E4*K) {
        int e = tid / K, r = tid - e*K;
        float s = 0.f;
        #pragma unroll
        for (int i = 0; i < K; i++) s += sadj[e][r*K + i];
        sdeg[e][r] = 1.f / (s + 1e-6f);
    }
    __syncthreads();
    for (int idx = tid; idx < E4*K*K; idx += KH) {
        int e = idx / (K*K), r = idx - e*(K*K);
        sadj[e][r] *= sdeg[e][r / K];
    }

    // h0 = x @ W_fi + b_fi
    float a0[E4];
    {
        float bv = b_fi[j];
        #pragma unroll
        for (int e = 0; e < E4; e++) a0[e] = bv;
    }
    #pragma unroll
    for (int c = 0; c < C; c++) {
        float w = W_fi[c*H + j];
        #pragma unroll
        for (int e = 0; e < E4; e++) a0[e] += sx[e][k*C + c] * w;
    }
    {
        float4 v = make_float4(a0[0], a0[1], a0[2], a0[3]);
        sh04[tid] = v;
        sh4[tid]  = v;
    }
    __syncthreads();

    for (int l = 0; l < L; l++) {
        const float* Wzl = Wz + l*H*H; const float* Uzl = Uz + l*H*H;
        const float* Wrl = Wr + l*H*H; const float* Url = Ur + l*H*H;
        const float* Whl = Wh + l*H*H; const float* Uhl = Uh + l*H*H;

        // m = adj_norm @ h
        float m[E4] = {0.f, 0.f, 0.f, 0.f};
        #pragma unroll
        for (int i = 0; i < K; i++) {
            float4 hv = sh4[i*H + j];
            m[0] += sadj[0][k*K + i] * hv.x;
            m[1] += sadj[1][k*K + i] * hv.y;
            m[2] += sadj[2][k*K + i] * hv.z;
            m[3] += sadj[3][k*K + i] * hv.w;
        }
        sm4[tid] = make_float4(m[0], m[1], m[2], m[3]);
        __syncthreads();

        // fused z, r gates + m @ Wh partial of n
        float az[E4], ar[E4], an[E4];
        {
            float bzv = bz[l*H + j], brv = br[l*H + j], bnv = bh[l*H + j];
            #pragma unroll
            for (int e = 0; e < E4; e++) { az[e] = bzv; ar[e] = brv; an[e] = bnv; }
        }
        #pragma unroll 4
        for (int i = 0; i < H; i++) {
            float wz = Wzl[i*H + j], uz = Uzl[i*H + j];
            float wr = Wrl[i*H + j], ur = Url[i*H + j];
            float wh = Whl[i*H + j];
            float4 mv = sm4[k*H + i];
            float4 hv = sh4[k*H + i];
            az[0] += mv.x*wz + hv.x*uz;  ar[0] += mv.x*wr + hv.x*ur;  an[0] += mv.x*wh;
            az[1] += mv.y*wz + hv.y*uz;  ar[1] += mv.y*wr + hv.y*ur;  an[1] += mv.y*wh;
            az[2] += mv.z*wz + hv.z*uz;  ar[2] += mv.z*wr + hv.z*ur;  an[2] += mv.z*wh;
            az[3] += mv.w*wz + hv.w*uz;  ar[3] += mv.w*wr + hv.w*ur;  an[3] += mv.w*wh;
        }
        float zg[E4], rg[E4];
        #pragma unroll
        for (int e = 0; e < E4; e++) {
            zg[e] = fast_sigmoid(az[e]);
            rg[e] = fast_sigmoid(ar[e]);
        }
        float4 hown = sh4[tid];
        srh4[tid] = make_float4(rg[0]*hown.x, rg[1]*hown.y, rg[2]*hown.z, rg[3]*hown.w);
        __syncthreads();

        // n gate remainder: (r*h) @ Uh
        #pragma unroll 4
        for (int i = 0; i < H; i++) {
            float uh = Uhl[i*H + j];
            float4 rv = srh4[k*H + i];
            an[0] += rv.x*uh;
            an[1] += rv.y*uh;
            an[2] += rv.z*uh;
            an[3] += rv.w*uh;
        }
        float4 h0v = sh04[tid];
        float4 hn;
        hn.x = (1.f - zg[0])*hown.x + zg[0]*fast_tanh(an[0]) + h0v.x;
        hn.y = (1.f - zg[1])*hown.y + zg[1]*fast_tanh(an[1]) + h0v.y;
        hn.z = (1.f - zg[2])*hown.z + zg[2]*fast_tanh(an[2]) + h0v.z;
        hn.w = (1.f - zg[3])*hown.w + zg[3]*fast_tanh(an[3]) + h0v.w;
        __syncthreads();
        sh4[tid] = hn;
        __syncthreads();
    }

    // Store comb, layout [t][kh][b]
    *(float4*)&g_comb[((size_t)t*KH + tid)*B + b0] = sh4[tid];
}

// ---------------------------------------------------------------------------
// GARU: persistent over all T. 128 blocks x 512 threads.
// tid = half*256 + g. Each thread accumulates ALL 8 batches over HALF of the
// reduction dimension; halves combine via smem. h lives in smem across steps.
// Dynamic smem layout (float4 units):
//   scomb4 [KH][2] | sgi4 [G][2] | sh4 [G][2] | srh4 [G][2] | sred [6][GT]
// ---------------------------------------------------------------------------
__global__ __launch_bounds__(GT, 1) void garu_kernel(
    const float* __restrict__ Wgp, const float* __restrict__ bgp,
    const float* __restrict__ Wgz, const float* __restrict__ Ugz, const float* __restrict__ bgz,
    const float* __restrict__ Wgr, const float* __restrict__ Ugr, const float* __restrict__ bgr,
    const float* __restrict__ Wgn, const float* __restrict__ Ugn, const float* __restrict__ bgn)
{
    extern __shared__ float4 dyn[];
    float4* scomb4 = dyn;                 // [KH*2], idx i*2+w
    float4* sgi4   = scomb4 + KH*2;       // [G*2]
    float4* sh4    = sgi4   + G*2;        // [G*2]
    float4* srh4   = sh4    + G*2;        // [G*2]
    float4* sred   = srh4   + G*2;        // [6*GT], slot s at sred + s*GT

    const int tid  = threadIdx.x;
    const int g    = tid & (G - 1);
    const int half = tid >> 8;
    const int b0   = blockIdx.x * GB;

    sh4[g*2 + half] = make_float4(0.f, 0.f, 0.f, 0.f);

    const float bgpv = bgp[g], bgzv = bgz[g], bgrv = bgr[g], bgnv = bgn[g];
    const float4 bgp4 = make_float4(bgpv, bgpv, bgpv, bgpv);

    for (int t = 0; t < T; t++) {
        // stage comb tile for this block's 8 batches (also fences last step's sh4)
        for (int idx = tid; idx < KH*2; idx += GT) {
            scomb4[idx] = *(const float4*)&g_comb[((size_t)t*KH + (idx >> 1))*B + b0 + 4*(idx & 1)];
        }
        __syncthreads();

        // gi = comb @ Wgp + bgp  -- split-K: half covers 160 of 320 rows, all 8 batches
        float ag[8] = {0,0,0,0,0,0,0,0};
        {
            const int i0 = half * (KH/2);
            #pragma unroll 4
            for (int i = i0; i < i0 + KH/2; i++) {
                float wp = Wgp[i*G + g];
                float4 c0 = scomb4[i*2 + 0];
                float4 c1 = scomb4[i*2 + 1];
                ag[0] += c0.x*wp; ag[1] += c0.y*wp; ag[2] += c0.z*wp; ag[3] += c0.w*wp;
                ag[4] += c1.x*wp; ag[5] += c1.y*wp; ag[6] += c1.z*wp; ag[7] += c1.w*wp;
            }
        }
        sred[0*GT + tid] = make_float4(ag[0], ag[1], ag[2], ag[3]);
        sred[1*GT + tid] = make_float4(ag[4], ag[5], ag[6], ag[7]);
        __syncthreads();
        // combine: thread (g,half) owns batch-group `half`
        sgi4[g*2 + half] = f4add(f4add(sred[half*GT + g], sred[half*GT + 256 + g]), bgp4);
        __syncthreads();

        // pass 1 (split-K over 128 of 256): z, r pre-acts + gi @ Wgn, all 8 batches
        float az[8] = {0,0,0,0,0,0,0,0};
        float ar[8] = {0,0,0,0,0,0,0,0};
        float an[8] = {0,0,0,0,0,0,0,0};
        {
            const int i0 = half * (G/2);
            #pragma unroll 2
            for (int i = i0; i < i0 + G/2; i++) {
                float wz = Wgz[i*G + g], uz = Ugz[i*G + g];
                float wr = Wgr[i*G + g], ur = Ugr[i*G + g];
                float wn = Wgn[i*G + g];
                float4 g0 = sgi4[i*2 + 0];
                float4 g1 = sgi4[i*2 + 1];
                float4 h0 = sh4[i*2 + 0];
                float4 h1 = sh4[i*2 + 1];
                az[0] += g0.x*wz + h0.x*uz;  ar[0] += g0.x*wr + h0.x*ur;  an[0] += g0.x*wn;
                az[1] += g0.y*wz + h0.y*uz;  ar[1] += g0.y*wr + h0.y*ur;  an[1] += g0.y*wn;
                az[2] += g0.z*wz + h0.z*uz;  ar[2] += g0.z*wr + h0.z*ur;  an[2] += g0.z*wn;
                az[3] += g0.w*wz + h0.w*uz;  ar[3] += g0.w*wr + h0.w*ur;  an[3] += g0.w*wn;
                az[4] += g1.x*wz + h1.x*uz;  ar[4] += g1.x*wr + h1.x*ur;  an[4] += g1.x*wn;
                az[5] += g1.y*wz + h1.y*uz;  ar[5] += g1.y*wr + h1.y*ur;  an[5] += g1.y*wn;
                az[6] += g1.z*wz + h1.z*uz;  ar[6] += g1.z*wr + h1.z*ur;  an[6] += g1.z*wn;
                az[7] += g1.w*wz + h1.w*uz;  ar[7] += g1.w*wr + h1.w*ur;  an[7] += g1.w*wn;
            }
        }
        sred[0*GT + tid] = make_float4(az[0], az[1], az[2], az[3]);
        sred[1*GT + tid] = make_float4(az[4], az[5], az[6], az[7]);
        sred[2*GT + tid] = make_float4(ar[0], ar[1], ar[2], ar[3]);
        sred[3*GT + tid] = make_float4(ar[4], ar[5], ar[6], ar[7]);
        sred[4*GT + tid] = make_float4(an[0], an[1], an[2], an[3]);
        sred[5*GT + tid] = make_float4(an[4], an[5], an[6], an[7]);
        __syncthreads();

        float4 az4 = f4add(sred[(0+half)*GT + g], sred[(0+half)*GT + 256 + g]);
        float4 ar4 = f4add(sred[(2+half)*GT + g], sred[(2+half)*GT + 256 + g]);
        float4 anp = f4add(sred[(4+half)*GT + g], sred[(4+half)*GT + 256 + g]);
        float4 hown = sh4[g*2 + half];
        float4 zz;
        zz.x = fast_sigmoid(az4.x + bgzv);  zz.y = fast_sigmoid(az4.y + bgzv);
        zz.z = fast_sigmoid(az4.z + bgzv);  zz.w = fast_sigmoid(az4.w + bgzv);
        {
            float r0 = fast_sigmoid(ar4.x + bgrv), r1 = fast_sigmoid(ar4.y + bgrv);
            float r2 = fast_sigmoid(ar4.z + bgrv), r3 = fast_sigmoid(ar4.w + bgrv);
            srh4[g*2 + half] = make_float4(r0*hown.x, r1*hown.y, r2*hown.z, r3*hown.w);
        }
        float4 antot = make_float4(anp.x + bgnv, anp.y + bgnv, anp.z + bgnv, anp.w + bgnv);
        __syncthreads();

        // pass 2 (split-K): (r*h) @ Ugn, all 8 batches
        float a2[8] = {0,0,0,0,0,0,0,0};
        {
            const int i0 = half * (G/2);
            #pragma unroll 4
            for (int i = i0; i < i0 + G/2; i++) {
                float un = Ugn[i*G + g];
                float4 s0 = srh4[i*2 + 0];
                float4 s1 = srh4[i*2 + 1];
                a2[0] += s0.x*un; a2[1] += s0.y*un; a2[2] += s0.z*un; a2[3] += s0.w*un;
                a2[4] += s1.x*un; a2[5] += s1.y*un; a2[6] += s1.z*un; a2[7] += s1.w*un;
            }
        }
        sred[0*GT + tid] = make_float4(a2[0], a2[1], a2[2], a2[3]);
        sred[1*GT + tid] = make_float4(a2[4], a2[5], a2[6], a2[7]);
        __syncthreads();
        {
            float4 p = f4add(sred[half*GT + g], sred[half*GT + 256 + g]);
            float4 hn;
            hn.x = (1.f - zz.x)*fast_tanh(antot.x + p.x) + zz.x*hown.x;
            hn.y = (1.f - zz.y)*fast_tanh(antot.y + p.y) + zz.y*hown.y;
            hn.z = (1.f - zz.z)*fast_tanh(antot.z + p.z) + zz.z*hown.z;
            hn.w = (1.f - zz.w)*fast_tanh(antot.w + p.w) + zz.w*hown.w;
            sh4[g*2 + half] = hn;   // fenced by next step's top barrier
        }
    }

    __syncthreads();
    // final hidden -> global (for classifier)
    float4 hv = sh4[g*2 + half];
    g_h[(size_t)(b0 + 4*half + 0)*G + g] = hv.x;
    g_h[(size_t)(b0 + 4*half + 1)*G + g] = hv.y;
    g_h[(size_t)(b0 + 4*half + 2)*G + g] = hv.z;
    g_h[(size_t)(b0 + 4*half + 3)*G + g] = hv.w;
}

// ---------------------------------------------------------------------------
// Classifier: one block per batch element, 64 threads (hidden dim).
// ---------------------------------------------------------------------------
__global__ __launch_bounds__(64) void cls_kernel(
    const float* __restrict__ W1, const float* __restrict__ b1,
    const float* __restrict__ W2, const float* __restrict__ b2,
    float* __restrict__ out)
{
    __shared__ float wsum[2];
    const int b = blockIdx.x;
    const int j = threadIdx.x;

    const float* hb = g_h + (size_t)b*G;
    float acc = b1[j];
    #pragma unroll 8
    for (int i = 0; i < G; i++) acc += hb[i] * W1[i*64 + j];
    float hid = fmaxf(acc, 0.f);
    float v = hid * W2[j];
    #pragma unroll
    for (int o = 16; o > 0; o >>= 1) v += __shfl_down_sync(0xffffffffu, v, o);
    if ((j & 31) == 0) wsum[j >> 5] = v;
    __syncthreads();
    if (j == 0) {
        float s = wsum[0] + wsum[1] + b2[0];
        out[b] = fast_sigmoid(s);
    }
}

extern "C" void kernel_launch(void* const* d_in, const int* in_sizes, int n_in,
                              void* d_out, int out_size)
{
    const float* x    = (const float*)d_in[0];
    const float* adj  = (const float*)d_in[1];
    const float* W_fi = (const float*)d_in[2];
    const float* b_fi = (const float*)d_in[3];
    const float* Wz   = (const float*)d_in[4];
    const float* Uz   = (const float*)d_in[5];
    const float* bz   = (const float*)d_in[6];
    const float* Wr   = (const float*)d_in[7];
    const float* Ur   = (const float*)d_in[8];
    const float* br   = (const float*)d_in[9];
    const float* Wh   = (const float*)d_in[10];
    const float* Uh   = (const float*)d_in[11];
    const float* bh   = (const float*)d_in[12];
    const float* Wgp  = (const float*)d_in[13];
    const float* bgp  = (const float*)d_in[14];
    const float* Wgz  = (const float*)d_in[15];
    const float* Ugz  = (const float*)d_in[16];
    const float* bgz  = (const float*)d_in[17];
    const float* Wgr  = (const float*)d_in[18];
    const float* Ugr  = (const float*)d_in[19];
    const float* bgr  = (const float*)d_in[20];
    const float* Wgn  = (const float*)d_in[21];
    const float* Ugn  = (const float*)d_in[22];
    const float* bgn  = (const float*)d_in[23];
    const float* W1   = (const float*)d_in[24];
    const float* b1   = (const float*)d_in[25];
    const float* W2   = (const float*)d_in[26];
    const float* b2   = (const float*)d_in[27];
    float* out = (float*)d_out;

    // GARU dynamic smem: scomb(640) + 3*(512) + sred(3072) float4s = 83,968 B
    const int garu_smem = (KH*2 + G*2*3 + 6*GT) * (int)sizeof(float4);
    static int attr_done = 0;
    if (!attr_done) {
        cudaFuncSetAttribute(garu_kernel,
                             cudaFuncAttributeMaxDynamicSharedMemorySize, garu_smem);
        attr_done = 1;
    }

    gnn_kernel<<<dim3(B/E4, T), KH>>>(x, adj, W_fi, b_fi,
                                      Wz, Uz, bz, Wr, Ur, br, Wh, Uh, bh);
    garu_kernel<<<B/GB, GT, garu_smem>>>(Wgp, bgp, Wgz, Ugz, bgz,
                                         Wgr, Ugr, bgr, Wgn, Ugn, bgn);
    cls_kernel<<<B, 64>>>(W1, b1, W2, b2, out);
}

// round 7
// speedup vs baseline: 3.6862x; 1.1250x over previous
#include <cuda_runtime.h>
#include <math.h>

#define T 96
#define B 1024
#define K 10
#define C 16
#define H 32
#define G 256
#define L 4
#define KH (K*H)     // 320
#define E4 4         // batch elements per GNN block
#define NBP 16       // batches per projection block
#define GB 8         // batches per recurrent block

typedef unsigned long long ull;

__device__ float g_comb[(size_t)T * KH * B];     // [t][kh][b]
__device__ float g_proj[(size_t)T * 3 * G * B];  // [t][s][g][b]
__device__ float g_h[B * G];
__device__ float g_wcat[KH * 3 * G];             // [i][s*G+j]
__device__ float g_bcat[3 * G];

__device__ __forceinline__ float fast_tanh(float x) {
    float y; asm("tanh.approx.f32 %0, %1;" : "=f"(y) : "f"(x)); return y;
}
__device__ __forceinline__ float fast_sigmoid(float x) {
    return fmaf(0.5f, fast_tanh(0.5f * x), 0.5f);
}
__device__ __forceinline__ ull pack1(float a) {
    ull r; asm("mov.b64 %0,{%1,%2};" : "=l"(r) : "f"(a), "f"(a)); return r;
}
__device__ __forceinline__ void unpack2(ull v, float& a, float& b) {
    asm("mov.b64 {%0,%1},%2;" : "=f"(a), "=f"(b) : "l"(v));
}
__device__ __forceinline__ ull fma2(ull a, ull b, ull c) {
    ull d; asm("fma.rn.f32x2 %0,%1,%2,%3;" : "=l"(d) : "l"(a), "l"(b), "l"(c)); return d;
}
__device__ __forceinline__ ull add2(ull a, ull b) {
    ull d; asm("add.rn.f32x2 %0,%1,%2;" : "=l"(d) : "l"(a), "l"(b)); return d;
}
__device__ __forceinline__ ulonglong2 add2v(ulonglong2 a, ulonglong2 b) {
    a.x = add2(a.x, b.x); a.y = add2(a.y, b.y); return a;
}

// ---------------------------------------------------------------------------
// Weight combine: Wcat[i][s*G+j] = sum_k Wgp[i][k]*Wg_s[k][j];
//                 bcat[s*G+j] = bg_s[j] + sum_k bgp[k]*Wg_s[k][j]
// ---------------------------------------------------------------------------
__global__ __launch_bounds__(G) void wcomb_kernel(
    const float* __restrict__ Wgp, const float* __restrict__ bgp,
    const float* __restrict__ Wgz, const float* __restrict__ bgz,
    const float* __restrict__ Wgr, const float* __restrict__ bgr,
    const float* __restrict__ Wgn, const float* __restrict__ bgn)
{
    __shared__ float sa[G], sb[G];
    const int i = blockIdx.x, s = blockIdx.y, j = threadIdx.x;
    const float* Ws = (s == 0) ? Wgz : (s == 1) ? Wgr : Wgn;
    const float* bs = (s == 0) ? bgz : (s == 1) ? bgr : bgn;

    sa[j] = Wgp[i*G + j];
    if (i == 0) sb[j] = bgp[j];
    __syncthreads();

    float acc = 0.f;
    #pragma unroll 8
    for (int k = 0; k < G; k++) acc += sa[k] * Ws[k*G + j];
    g_wcat[i*(3*G) + s*G + j] = acc;

    if (i == 0) {
        float bacc = bs[j];
        #pragma unroll 8
        for (int k = 0; k < G; k++) bacc += sb[k] * Ws[k*G + j];
        g_bcat[s*G + j] = bacc;
    }
}

// ---------------------------------------------------------------------------
// GNN: grid (B/E4, T), 320 threads = (k,j). 4 batch elements per block.
// (unchanged from the proven R4 version)
// ---------------------------------------------------------------------------
__global__ __launch_bounds__(KH) void gnn_kernel(
    const float* __restrict__ x, const float* __restrict__ adj,
    const float* __restrict__ W_fi, const float* __restrict__ b_fi,
    const float* __restrict__ Wz, const float* __restrict__ Uz, const float* __restrict__ bz,
    const float* __restrict__ Wr, const float* __restrict__ Ur, const float* __restrict__ br,
    const float* __restrict__ Wh, const float* __restrict__ Uh, const float* __restrict__ bh)
{
    __shared__ float  sx[E4][K*C];
    __shared__ float  sadj[E4][K*K];
    __shared__ float  sdeg[E4][K];
    __shared__ float4 sh4[KH], sh04[KH], sm4[KH], srh4[KH];

    const int b0  = blockIdx.x * E4;
    const int t   = blockIdx.y;
    const int tid = threadIdx.x;
    const int k   = tid >> 5;
    const int j   = tid & 31;

    for (int idx = tid; idx < E4*K*C; idx += KH) {
        int e = idx / (K*C), r = idx - e*(K*C);
        sx[e][r] = x[((size_t)t*B + b0 + e)*(K*C) + r];
    }
    for (int idx = tid; idx < E4*K*K; idx += KH) {
        int e = idx / (K*K), r = idx - e*(K*K);
        int row = r / K, col = r - row*K;
        sadj[e][r] = adj[((size_t)t*B + b0 + e)*(K*K) + r] + (row == col ? 1.f : 0.f);
    }
    __syncthreads();
    if (tid < E4*K) {
        int e = tid / K, r = tid - e*K;
        float s = 0.f;
        #pragma unroll
        for (int i = 0; i < K; i++) s += sadj[e][r*K + i];
        sdeg[e][r] = 1.f / (s + 1e-6f);
    }
    __syncthreads();
    for (int idx = tid; idx < E4*K*K; idx += KH) {
        int e = idx / (K*K), r = idx - e*(K*K);
        sadj[e][r] *= sdeg[e][r / K];
    }

    float a0[E4];
    {
        float bv = b_fi[j];
        #pragma unroll
        for (int e = 0; e < E4; e++) a0[e] = bv;
    }
    #pragma unroll
    for (int c = 0; c < C; c++) {
        float w = W_fi[c*H + j];
        #pragma unroll
        for (int e = 0; e < E4; e++) a0[e] += sx[e][k*C + c] * w;
    }
    {
        float4 v = make_float4(a0[0], a0[1], a0[2], a0[3]);
        sh04[tid] = v;
        sh4[tid]  = v;
    }
    __syncthreads();

    for (int l = 0; l < L; l++) {
        const float* Wzl = Wz + l*H*H; const float* Uzl = Uz + l*H*H;
        const float* Wrl = Wr + l*H*H; const float* Url = Ur + l*H*H;
        const float* Whl = Wh + l*H*H; const float* Uhl = Uh + l*H*H;

        float m[E4] = {0.f, 0.f, 0.f, 0.f};
        #pragma unroll
        for (int i = 0; i < K; i++) {
            float4 hv = sh4[i*H + j];
            m[0] += sadj[0][k*K + i] * hv.x;
            m[1] += sadj[1][k*K + i] * hv.y;
            m[2] += sadj[2][k*K + i] * hv.z;
            m[3] += sadj[3][k*K + i] * hv.w;
        }
        sm4[tid] = make_float4(m[0], m[1], m[2], m[3]);
        __syncthreads();

        float az[E4], ar[E4], an[E4];
        {
            float bzv = bz[l*H + j], brv = br[l*H + j], bnv = bh[l*H + j];
            #pragma unroll
            for (int e = 0; e < E4; e++) { az[e] = bzv; ar[e] = brv; an[e] = bnv; }
        }
        #pragma unroll 4
        for (int i = 0; i < H; i++) {
            float wz = Wzl[i*H + j], uz = Uzl[i*H + j];
            float wr = Wrl[i*H + j], ur = Url[i*H + j];
            float wh = Whl[i*H + j];
            float4 mv = sm4[k*H + i];
            float4 hv = sh4[k*H + i];
            az[0] += mv.x*wz + hv.x*uz;  ar[0] += mv.x*wr + hv.x*ur;  an[0] += mv.x*wh;
            az[1] += mv.y*wz + hv.y*uz;  ar[1] += mv.y*wr + hv.y*ur;  an[1] += mv.y*wh;
            az[2] += mv.z*wz + hv.z*uz;  ar[2] += mv.z*wr + hv.z*ur;  an[2] += mv.z*wh;
            az[3] += mv.w*wz + hv.w*uz;  ar[3] += mv.w*wr + hv.w*ur;  an[3] += mv.w*wh;
        }
        float zg[E4], rg[E4];
        #pragma unroll
        for (int e = 0; e < E4; e++) {
            zg[e] = fast_sigmoid(az[e]);
            rg[e] = fast_sigmoid(ar[e]);
        }
        float4 hown = sh4[tid];
        srh4[tid] = make_float4(rg[0]*hown.x, rg[1]*hown.y, rg[2]*hown.z, rg[3]*hown.w);
        __syncthreads();

        #pragma unroll 4
        for (int i = 0; i < H; i++) {
            float uh = Uhl[i*H + j];
            float4 rv = srh4[k*H + i];
            an[0] += rv.x*uh; an[1] += rv.y*uh; an[2] += rv.z*uh; an[3] += rv.w*uh;
        }
        float4 h0v = sh04[tid];
        float4 hn;
        hn.x = (1.f - zg[0])*hown.x + zg[0]*fast_tanh(an[0]) + h0v.x;
        hn.y = (1.f - zg[1])*hown.y + zg[1]*fast_tanh(an[1]) + h0v.y;
        hn.z = (1.f - zg[2])*hown.z + zg[2]*fast_tanh(an[2]) + h0v.z;
        hn.w = (1.f - zg[3])*hown.w + zg[3]*fast_tanh(an[3]) + h0v.w;
        __syncthreads();
        sh4[tid] = hn;
        __syncthreads();
    }

    *(float4*)&g_comb[((size_t)t*KH + tid)*B + b0] = sh4[tid];
}

// ---------------------------------------------------------------------------
// Projection: g_proj[t][s][g][b] = comb[t][:,b] @ Wcat[:, s*G+g] + bcat[s*G+g]
// grid (B/NBP, T), 256 threads (one per column g), packed f32x2 over batch.
// ---------------------------------------------------------------------------
__global__ __launch_bounds__(G) void proj_kernel()
{
    __shared__ ulonglong2 scomb[KH][NBP/4];   // [row][batch-quad], 20KB

    const int g  = threadIdx.x;
    const int b0 = blockIdx.x * NBP;
    const int t  = blockIdx.y;

    for (int idx = g; idx < KH*(NBP/4); idx += G) {
        int row = idx >> 2, p = idx & 3;
        scomb[row][p] = *(const ulonglong2*)&g_comb[((size_t)t*KH + row)*B + b0 + 4*p];
    }
    __syncthreads();

    #pragma unroll
    for (int s = 0; s < 3; s++) {
        ull acc[8];
        {
            ull bv = pack1(g_bcat[s*G + g]);
            #pragma unroll
            for (int q = 0; q < 8; q++) acc[q] = bv;
        }
        const float* wcol = g_wcat + s*G + g;
        #pragma unroll 4
        for (int i = 0; i < KH; i++) {
            ull w2 = pack1(wcol[i*(3*G)]);
            #pragma unroll
            for (int p = 0; p < 4; p++) {
                ulonglong2 c = scomb[i][p];
                acc[2*p]   = fma2(c.x, w2, acc[2*p]);
                acc[2*p+1] = fma2(c.y, w2, acc[2*p+1]);
            }
        }
        ulonglong2* dst = (ulonglong2*)&g_proj[(((size_t)t*3 + s)*G + g)*B + b0];
        #pragma unroll
        for (int p = 0; p < 4; p++) dst[p] = make_ulonglong2(acc[2*p], acc[2*p+1]);
    }
}

// ---------------------------------------------------------------------------
// Recurrent GARU: 128 blocks x 512 threads, 8 batches/block, split-K halves.
// Only h@Ugz, h@Ugr, (r*h)@Ugn remain; gate inputs come from g_proj.
// Dynamic smem (ulonglong2): sh[256][2] | srh[256][2] | sred[2][2][256][2]
// ---------------------------------------------------------------------------
__global__ __launch_bounds__(512, 1) void recur_kernel(
    const float* __restrict__ Ugz, const float* __restrict__ Ugr,
    const float* __restrict__ Ugn)
{
    extern __shared__ ulonglong2 dyn2[];
    ulonglong2* sh   = dyn2;            // [g*2 + j]
    ulonglong2* srh  = sh  + G*2;
    ulonglong2* sred = srh + G*2;       // [((q*2+hf)*G + g)*2 + j]

    const int tid  = threadIdx.x;
    const int g    = tid & (G - 1);
    const int half = tid >> 8;
    const int b0   = blockIdx.x * GB;

    sh[g*2 + half] = make_ulonglong2(0ULL, 0ULL);
    __syncthreads();

    for (int t = 0; t < T; t++) {
        // pass 1: partial h@Ugz, h@Ugr over this half's 128 rows
        ull az0=0, az1=0, az2=0, az3=0, ar0=0, ar1=0, ar2=0, ar3=0;
        {
            const int i0 = half * (G/2);
            #pragma unroll 2
            for (int i = i0; i < i0 + G/2; i++) {
                ull uz2 = pack1(Ugz[i*G + g]);
                ull ur2 = pack1(Ugr[i*G + g]);
                ulonglong2 h0 = sh[i*2 + 0];
                ulonglong2 h1 = sh[i*2 + 1];
                az0 = fma2(h0.x, uz2, az0); az1 = fma2(h0.y, uz2, az1);
                az2 = fma2(h1.x, uz2, az2); az3 = fma2(h1.y, uz2, az3);
                ar0 = fma2(h0.x, ur2, ar0); ar1 = fma2(h0.y, ur2, ar1);
                ar2 = fma2(h1.x, ur2, ar2); ar3 = fma2(h1.y, ur2, ar3);
            }
        }
        sred[((0*2 + half)*G + g)*2 + 0] = make_ulonglong2(az0, az1);
        sred[((0*2 + half)*G + g)*2 + 1] = make_ulonglong2(az2, az3);
        sred[((1*2 + half)*G + g)*2 + 0] = make_ulonglong2(ar0, ar1);
        sred[((1*2 + half)*G + g)*2 + 1] = make_ulonglong2(ar2, ar3);
        __syncthreads();

        // combine: thread (g,half) owns batch-quad `half` (batches 4*half..4*half+3)
        ulonglong2 zp = add2v(sred[((0*2+0)*G + g)*2 + half], sred[((0*2+1)*G + g)*2 + half]);
        ulonglong2 rp = add2v(sred[((1*2+0)*G + g)*2 + half], sred[((1*2+1)*G + g)*2 + half]);
        const size_t pbase = (((size_t)t*3)*G + g)*B + b0 + 4*half;
        zp = add2v(zp, *(const ulonglong2*)&g_proj[pbase]);
        rp = add2v(rp, *(const ulonglong2*)&g_proj[pbase + (size_t)G*B]);
        ulonglong2 pn = *(const ulonglong2*)&g_proj[pbase + (size_t)2*G*B];

        float zf[4], rf[4], hf[4];
        unpack2(zp.x, zf[0], zf[1]); unpack2(zp.y, zf[2], zf[3]);
        unpack2(rp.x, rf[0], rf[1]); unpack2(rp.y, rf[2], rf[3]);
        ulonglong2 hold = sh[g*2 + half];
        unpack2(hold.x, hf[0], hf[1]); unpack2(hold.y, hf[2], hf[3]);
        #pragma unroll
        for (int e = 0; e < 4; e++) {
            zf[e] = fast_sigmoid(zf[e]);
            rf[e] = fast_sigmoid(rf[e]) * hf[e];   // r*h
        }
        {
            ull s0, s1;
            asm("mov.b64 %0,{%1,%2};" : "=l"(s0) : "f"(rf[0]), "f"(rf[1]));
            asm("mov.b64 %0,{%1,%2};" : "=l"(s1) : "f"(rf[2]), "f"(rf[3]));
            srh[g*2 + half] = make_ulonglong2(s0, s1);
        }
        __syncthreads();

        // pass 2: partial (r*h)@Ugn
        ull an0=0, an1=0, an2=0, an3=0;
        {
            const int i0 = half * (G/2);
            #pragma unroll 4
            for (int i = i0; i < i0 + G/2; i++) {
                ull un2 = pack1(Ugn[i*G + g]);
                ulonglong2 s0 = srh[i*2 + 0];
                ulonglong2 s1 = srh[i*2 + 1];
                an0 = fma2(s0.x, un2, an0); an1 = fma2(s0.y, un2, an1);
                an2 = fma2(s1.x, un2, an2); an3 = fma2(s1.y, un2, an3);
            }
        }
        sred[((0*2 + half)*G + g)*2 + 0] = make_ulonglong2(an0, an1);
        sred[((0*2 + half)*G + g)*2 + 1] = make_ulonglong2(an2, an3);
        __syncthreads();

        ulonglong2 ap = add2v(sred[((0*2+0)*G + g)*2 + half], sred[((0*2+1)*G + g)*2 + half]);
        ap = add2v(ap, pn);
        float af[4];
        unpack2(ap.x, af[0], af[1]); unpack2(ap.y, af[2], af[3]);
        float hn[4];
        #pragma unroll
        for (int e = 0; e < 4; e++)
            hn[e] = (1.f - zf[e]) * fast_tanh(af[e]) + zf[e] * hf[e];
        {
            ull s0, s1;
            asm("mov.b64 %0,{%1,%2};" : "=l"(s0) : "f"(hn[0]), "f"(hn[1]));
            asm("mov.b64 %0,{%1,%2};" : "=l"(s1) : "f"(hn[2]), "f"(hn[3]));
            sh[g*2 + half] = make_ulonglong2(s0, s1);
        }
        __syncthreads();
    }

    // final hidden -> global
    float hf[4];
    ulonglong2 hv = sh[g*2 + half];
    unpack2(hv.x, hf[0], hf[1]); unpack2(hv.y, hf[2], hf[3]);
    #pragma unroll
    for (int e = 0; e < 4; e++)
        g_h[(size_t)(b0 + 4*half + e)*G + g] = hf[e];
}

// ---------------------------------------------------------------------------
// Classifier
// ---------------------------------------------------------------------------
__global__ __launch_bounds__(64) void cls_kernel(
    const float* __restrict__ W1, const float* __restrict__ b1,
    const float* __restrict__ W2, const float* __restrict__ b2,
    float* __restrict__ out)
{
    __shared__ float wsum[2];
    const int b = blockIdx.x;
    const int j = threadIdx.x;

    const float* hb = g_h + (size_t)b*G;
    float acc = b1[j];
    #pragma unroll 8
    for (int i = 0; i < G; i++) acc += hb[i] * W1[i*64 + j];
    float hid = fmaxf(acc, 0.f);
    float v = hid * W2[j];
    #pragma unroll
    for (int o = 16; o > 0; o >>= 1) v += __shfl_down_sync(0xffffffffu, v, o);
    if ((j & 31) == 0) wsum[j >> 5] = v;
    __syncthreads();
    if (j == 0) out[b] = fast_sigmoid(wsum[0] + wsum[1] + b2[0]);
}

extern "C" void kernel_launch(void* const* d_in, const int* in_sizes, int n_in,
                              void* d_out, int out_size)
{
    const float* x    = (const float*)d_in[0];
    const float* adj  = (const float*)d_in[1];
    const float* W_fi = (const float*)d_in[2];
    const float* b_fi = (const float*)d_in[3];
    const float* Wz   = (const float*)d_in[4];
    const float* Uz   = (const float*)d_in[5];
    const float* bz   = (const float*)d_in[6];
    const float* Wr   = (const float*)d_in[7];
    const float* Ur   = (const float*)d_in[8];
    const float* br   = (const float*)d_in[9];
    const float* Wh   = (const float*)d_in[10];
    const float* Uh   = (const float*)d_in[11];
    const float* bh   = (const float*)d_in[12];
    const float* Wgp  = (const float*)d_in[13];
    const float* bgp  = (const float*)d_in[14];
    const float* Wgz  = (const float*)d_in[15];
    const float* Ugz  = (const float*)d_in[16];
    const float* bgz  = (const float*)d_in[17];
    const float* Wgr  = (const float*)d_in[18];
    const float* Ugr  = (const float*)d_in[19];
    const float* bgr  = (const float*)d_in[20];
    const float* Wgn  = (const float*)d_in[21];
    const float* Ugn  = (const float*)d_in[22];
    const float* bgn  = (const float*)d_in[23];
    const float* W1   = (const float*)d_in[24];
    const float* b1   = (const float*)d_in[25];
    const float* W2   = (const float*)d_in[26];
    const float* b2   = (const float*)d_in[27];
    float* out = (float*)d_out;

    const int recur_smem = (G*2*2 + 2*2*G*2) * (int)sizeof(ulonglong2);  // 48KB
    static int attr_done = 0;
    if (!attr_done) {
        cudaFuncSetAttribute(recur_kernel,
                             cudaFuncAttributeMaxDynamicSharedMemorySize, recur_smem);
        attr_done = 1;
    }

    wcomb_kernel<<<dim3(KH, 3), G>>>(Wgp, bgp, Wgz, bgz, Wgr, bgr, Wgn, bgn);
    gnn_kernel<<<dim3(B/E4, T), KH>>>(x, adj, W_fi, b_fi,
                                      Wz, Uz, bz, Wr, Ur, br, Wh, Uh, bh);
    proj_kernel<<<dim3(B/NBP, T), G>>>();
    recur_kernel<<<B/GB, 512, recur_smem>>>(Ugz, Ugr, Ugn);
    cls_kernel<<<B, 64>>>(W1, b1, W2, b2, out);
}

// round 8
// speedup vs baseline: 4.0921x; 1.1101x over previous
#include <cuda_runtime.h>
#include <math.h>

#define T 96
#define B 1024
#define K 10
#define C 16
#define H 32
#define G 256
#define L 4
#define KH (K*H)     // 320
#define E4 4         // batch elements per GNN block
#define NBP 16       // batches per projection block
#define GB 8         // batches per recurrent block
#define RT 1024      // recurrent threads (256 cols x 4 reduction quarters)

typedef unsigned long long ull;

__device__ float g_comb[(size_t)T * KH * B];     // [t][kh][b]
__device__ float g_proj[(size_t)T * 3 * G * B];  // [t][s][g][b]
__device__ float g_h[B * G];
__device__ float g_wcatT[3 * G * KH];            // [(s*G+j)][i]  (transposed)
__device__ float g_bcat[3 * G];

__device__ __forceinline__ float fast_tanh(float x) {
    float y; asm("tanh.approx.f32 %0, %1;" : "=f"(y) : "f"(x)); return y;
}
__device__ __forceinline__ float fast_sigmoid(float x) {
    return fmaf(0.5f, fast_tanh(0.5f * x), 0.5f);
}
__device__ __forceinline__ ull pack2(float a, float b) {
    ull r; asm("mov.b64 %0,{%1,%2};" : "=l"(r) : "f"(a), "f"(b)); return r;
}
__device__ __forceinline__ ull pack1(float a) { return pack2(a, a); }
__device__ __forceinline__ void unpack2(ull v, float& a, float& b) {
    asm("mov.b64 {%0,%1},%2;" : "=f"(a), "=f"(b) : "l"(v));
}
__device__ __forceinline__ ull fma2(ull a, ull b, ull c) {
    ull d; asm("fma.rn.f32x2 %0,%1,%2,%3;" : "=l"(d) : "l"(a), "l"(b), "l"(c)); return d;
}
__device__ __forceinline__ ull add2(ull a, ull b) {
    ull d; asm("add.rn.f32x2 %0,%1,%2;" : "=l"(d) : "l"(a), "l"(b)); return d;
}
__device__ __forceinline__ ulonglong2 add2v(ulonglong2 a, ulonglong2 b) {
    a.x = add2(a.x, b.x); a.y = add2(a.y, b.y); return a;
}

// ---------------------------------------------------------------------------
// Weight combine (transposed output):
//   WcatT[(s*G+j)][i] = sum_k Wgp[i][k]*Wg_s[k][j]
//   bcat[s*G+j]       = bg_s[j] + sum_k bgp[k]*Wg_s[k][j]
// ---------------------------------------------------------------------------
__global__ __launch_bounds__(G) void wcomb_kernel(
    const float* __restrict__ Wgp, const float* __restrict__ bgp,
    const float* __restrict__ Wgz, const float* __restrict__ bgz,
    const float* __restrict__ Wgr, const float* __restrict__ bgr,
    const float* __restrict__ Wgn, const float* __restrict__ bgn)
{
    __shared__ float sa[G], sb[G];
    const int i = blockIdx.x, s = blockIdx.y, j = threadIdx.x;
    const float* Ws = (s == 0) ? Wgz : (s == 1) ? Wgr : Wgn;
    const float* bs = (s == 0) ? bgz : (s == 1) ? bgr : bgn;

    sa[j] = Wgp[i*G + j];
    if (i == 0) sb[j] = bgp[j];
    __syncthreads();

    float acc = 0.f;
    #pragma unroll 8
    for (int k = 0; k < G; k++) acc += sa[k] * Ws[k*G + j];
    g_wcatT[(s*G + j)*KH + i] = acc;

    if (i == 0) {
        float bacc = bs[j];
        #pragma unroll 8
        for (int k = 0; k < G; k++) bacc += sb[k] * Ws[k*G + j];
        g_bcat[s*G + j] = bacc;
    }
}

// ---------------------------------------------------------------------------
// GNN: grid (B/E4, T), 320 threads = (k,j). 4 batch elements per block.
// Packed-pair gates: {m,h} in smh, {wz,uz} packed -> one fma2 per term pair.
// ---------------------------------------------------------------------------
__global__ __launch_bounds__(KH, 3) void gnn_kernel(
    const float* __restrict__ x, const float* __restrict__ adj,
    const float* __restrict__ W_fi, const float* __restrict__ b_fi,
    const float* __restrict__ Wz, const float* __restrict__ Uz, const float* __restrict__ bz,
    const float* __restrict__ Wr, const float* __restrict__ Ur, const float* __restrict__ br,
    const float* __restrict__ Wh, const float* __restrict__ Uh, const float* __restrict__ bh)
{
    __shared__ float      sx[E4][K*C];
    __shared__ float      sadj[E4][K*K];
    __shared__ float      sdeg[E4][K];
    __shared__ ulonglong2 sadjT[K*K];      // {{a0,a1},{a2,a3}} per (k,i)
    __shared__ float4     sh4[KH], sh04[KH], srh4[KH];
    __shared__ ull        smh[KH][4];      // {m_e, h_e} per batch e

    const int b0  = blockIdx.x * E4;
    const int t   = blockIdx.y;
    const int tid = threadIdx.x;
    const int k   = tid >> 5;
    const int j   = tid & 31;

    for (int idx = tid; idx < E4*K*C; idx += KH) {
        int e = idx / (K*C), r = idx - e*(K*C);
        sx[e][r] = x[((size_t)t*B + b0 + e)*(K*C) + r];
    }
    for (int idx = tid; idx < E4*K*K; idx += KH) {
        int e = idx / (K*K), r = idx - e*(K*K);
        int row = r / K, col = r - row*K;
        sadj[e][r] = adj[((size_t)t*B + b0 + e)*(K*K) + r] + (row == col ? 1.f : 0.f);
    }
    __syncthreads();
    if (tid < E4*K) {
        int e = tid / K, r = tid - e*K;
        float s = 0.f;
        #pragma unroll
        for (int i = 0; i < K; i++) s += sadj[e][r*K + i];
        sdeg[e][r] = 1.f / (s + 1e-6f);
    }
    __syncthreads();
    for (int idx = tid; idx < E4*K*K; idx += KH) {
        int e = idx / (K*K), r = idx - e*(K*K);
        sadj[e][r] *= sdeg[e][r / K];
    }
    __syncthreads();
    if (tid < K*K) {
        sadjT[tid] = make_ulonglong2(pack2(sadj[0][tid], sadj[1][tid]),
                                     pack2(sadj[2][tid], sadj[3][tid]));
    }

    // h0 = x @ W_fi + b_fi
    float a0[E4];
    {
        float bv = b_fi[j];
        #pragma unroll
        for (int e = 0; e < E4; e++) a0[e] = bv;
    }
    #pragma unroll
    for (int c = 0; c < C; c++) {
        float w = W_fi[c*H + j];
        #pragma unroll
        for (int e = 0; e < E4; e++) a0[e] += sx[e][k*C + c] * w;
    }
    {
        float4 v = make_float4(a0[0], a0[1], a0[2], a0[3]);
        sh04[tid] = v;
        sh4[tid]  = v;
    }
    __syncthreads();

    for (int l = 0; l < L; l++) {
        const float* Wzl = Wz + l*H*H; const float* Uzl = Uz + l*H*H;
        const float* Wrl = Wr + l*H*H; const float* Url = Ur + l*H*H;
        const float* Whl = Wh + l*H*H; const float* Uhl = Uh + l*H*H;

        // m = adj_norm @ h (packed pairs over batch)
        ull mp01 = 0ULL, mp23 = 0ULL;
        #pragma unroll
        for (int i = 0; i < K; i++) {
            ulonglong2 a2 = sadjT[k*K + i];
            ulonglong2 h2 = *(const ulonglong2*)&sh4[i*H + j];
            mp01 = fma2(a2.x, h2.x, mp01);
            mp23 = fma2(a2.y, h2.y, mp23);
        }
        float4 hown = sh4[tid];
        {
            float m0, m1, m2, m3;
            unpack2(mp01, m0, m1); unpack2(mp23, m2, m3);
            *(ulonglong2*)&smh[tid][0] =
                make_ulonglong2(pack2(m0, hown.x), pack2(m1, hown.y));
            *(ulonglong2*)&smh[tid][2] =
                make_ulonglong2(pack2(m2, hown.z), pack2(m3, hown.w));
        }
        __syncthreads();

        // gates: az_e = dot({m,h},{wz,uz}) lanes; same for r; n gets m@Wh via {wh,0}
        ull azp[E4] = {0,0,0,0}, arp[E4] = {0,0,0,0}, anp[E4] = {0,0,0,0};
        #pragma unroll 4
        for (int i = 0; i < H; i++) {
            ull wzu = pack2(Wzl[i*H + j], Uzl[i*H + j]);
            ull wru = pack2(Wrl[i*H + j], Url[i*H + j]);
            ull wh0 = pack2(Whl[i*H + j], 0.f);
            ulonglong2 c01 = *(const ulonglong2*)&smh[k*H + i][0];
            ulonglong2 c23 = *(const ulonglong2*)&smh[k*H + i][2];
            azp[0] = fma2(c01.x, wzu, azp[0]);  azp[1] = fma2(c01.y, wzu, azp[1]);
            azp[2] = fma2(c23.x, wzu, azp[2]);  azp[3] = fma2(c23.y, wzu, azp[3]);
            arp[0] = fma2(c01.x, wru, arp[0]);  arp[1] = fma2(c01.y, wru, arp[1]);
            arp[2] = fma2(c23.x, wru, arp[2]);  arp[3] = fma2(c23.y, wru, arp[3]);
            anp[0] = fma2(c01.x, wh0, anp[0]);  anp[1] = fma2(c01.y, wh0, anp[1]);
            anp[2] = fma2(c23.x, wh0, anp[2]);  anp[3] = fma2(c23.y, wh0, anp[3]);
        }
        float zg[E4], rg[E4], anf[E4];
        {
            float bzv = bz[l*H + j], brv = br[l*H + j], bnv = bh[l*H + j];
            #pragma unroll
            for (int e = 0; e < E4; e++) {
                float a, b;
                unpack2(azp[e], a, b);  zg[e] = fast_sigmoid(a + b + bzv);
                unpack2(arp[e], a, b);  rg[e] = fast_sigmoid(a + b + brv);
                unpack2(anp[e], a, b);  anf[e] = a + b + bnv;
            }
        }
        srh4[tid] = make_float4(rg[0]*hown.x, rg[1]*hown.y, rg[2]*hown.z, rg[3]*hown.w);
        __syncthreads();

        // n remainder: (r*h) @ Uh (scalar, H=32)
        #pragma unroll 4
        for (int i = 0; i < H; i++) {
            float uh = Uhl[i*H + j];
            float4 rv = srh4[k*H + i];
            anf[0] += rv.x*uh; anf[1] += rv.y*uh; anf[2] += rv.z*uh; anf[3] += rv.w*uh;
        }
        float4 h0v = sh04[tid];
        float4 hn;
        hn.x = (1.f - zg[0])*hown.x + zg[0]*fast_tanh(anf[0]) + h0v.x;
        hn.y = (1.f - zg[1])*hown.y + zg[1]*fast_tanh(anf[1]) + h0v.y;
        hn.z = (1.f - zg[2])*hown.z + zg[2]*fast_tanh(anf[2]) + h0v.z;
        hn.w = (1.f - zg[3])*hown.w + zg[3]*fast_tanh(anf[3]) + h0v.w;
        __syncthreads();
        sh4[tid] = hn;
        __syncthreads();
    }

    *(float4*)&g_comb[((size_t)t*KH + tid)*B + b0] = sh4[tid];
}

// ---------------------------------------------------------------------------
// Projection: g_proj[t][s][g][b] = comb[t][:,b] @ WcatT[s*G+g][:] + bcat
// grid (B/NBP, T), 256 threads. s-fused, vectorized weight loads.
// ---------------------------------------------------------------------------
__global__ __launch_bounds__(G, 2) void proj_kernel()
{
    __shared__ ulonglong2 scomb[KH][NBP/4];   // 20KB

    const int g  = threadIdx.x;
    const int b0 = blockIdx.x * NBP;
    const int t  = blockIdx.y;

    for (int idx = g; idx < KH*(NBP/4); idx += G) {
        int row = idx >> 2, p = idx & 3;
        scomb[row][p] = *(const ulonglong2*)&g_comb[((size_t)t*KH + row)*B + b0 + 4*p];
    }
    __syncthreads();

    ull acc[3][8];
    #pragma unroll
    for (int s = 0; s < 3; s++) {
        ull bv = pack1(g_bcat[s*G + g]);
        #pragma unroll
        for (int q = 0; q < 8; q++) acc[s][q] = bv;
    }
    const float* w0 = g_wcatT + (0*G + g)*KH;
    const float* w1 = g_wcatT + (1*G + g)*KH;
    const float* w2 = g_wcatT + (2*G + g)*KH;

    #pragma unroll 2
    for (int i = 0; i < KH; i += 4) {
        float4 wa = *(const float4*)(w0 + i);
        float4 wb = *(const float4*)(w1 + i);
        float4 wc = *(const float4*)(w2 + i);
        #pragma unroll
        for (int u = 0; u < 4; u++) {
            float wav = (u==0)?wa.x:(u==1)?wa.y:(u==2)?wa.z:wa.w;
            float wbv = (u==0)?wb.x:(u==1)?wb.y:(u==2)?wb.z:wb.w;
            float wcv = (u==0)?wc.x:(u==1)?wc.y:(u==2)?wc.z:wc.w;
            ull wa2 = pack1(wav), wb2 = pack1(wbv), wc2 = pack1(wcv);
            #pragma unroll
            for (int p = 0; p < 4; p++) {
                ulonglong2 c = scomb[i + u][p];
                acc[0][2*p]   = fma2(c.x, wa2, acc[0][2*p]);
                acc[0][2*p+1] = fma2(c.y, wa2, acc[0][2*p+1]);
                acc[1][2*p]   = fma2(c.x, wb2, acc[1][2*p]);
                acc[1][2*p+1] = fma2(c.y, wb2, acc[1][2*p+1]);
                acc[2][2*p]   = fma2(c.x, wc2, acc[2][2*p]);
                acc[2][2*p+1] = fma2(c.y, wc2, acc[2][2*p+1]);
            }
        }
    }
    #pragma unroll
    for (int s = 0; s < 3; s++) {
        ulonglong2* dst = (ulonglong2*)&g_proj[(((size_t)t*3 + s)*G + g)*B + b0];
        #pragma unroll
        for (int p = 0; p < 4; p++) dst[p] = make_ulonglong2(acc[s][2*p], acc[s][2*p+1]);
    }
}

// ---------------------------------------------------------------------------
// Recurrent GARU: 128 blocks x 1024 threads, 8 batches/block.
// 4-way split-K over the 256 reduction rows (64 iters/quarter).
// smem (ulonglong2): sh[512] | srh[512] | sred[2][4][256][2]  = 82KB
// ---------------------------------------------------------------------------
__global__ __launch_bounds__(RT, 1) void recur_kernel(
    const float* __restrict__ Ugz, const float* __restrict__ Ugr,
    const float* __restrict__ Ugn)
{
    extern __shared__ ulonglong2 dyn2[];
    ulonglong2* sh   = dyn2;            // [col*2 + half]
    ulonglong2* srh  = sh  + 512;
    ulonglong2* sred = srh + 512;       // [((gate*4 + q)*G + col)*2 + half]

    const int tid = threadIdx.x;
    const int g   = tid & (G - 1);
    const int q   = tid >> 8;           // reduction quarter 0..3
    const int b0  = blockIdx.x * GB;
    const int i0  = q * (G/4);

    if (tid < 512) sh[tid] = make_ulonglong2(0ULL, 0ULL);
    __syncthreads();

    float zf[4], hf[4];
    ulonglong2 pn = make_ulonglong2(0ULL, 0ULL);

    for (int t = 0; t < T; t++) {
        // pass 1: partial h@Ugz, h@Ugr over this quarter's 64 rows
        ull az[4] = {0,0,0,0}, ar[4] = {0,0,0,0};
        #pragma unroll 4
        for (int i = i0; i < i0 + G/4; i++) {
            ull uz2 = pack1(Ugz[i*G + g]);
            ull ur2 = pack1(Ugr[i*G + g]);
            ulonglong2 h0 = sh[i*2 + 0];
            ulonglong2 h1 = sh[i*2 + 1];
            az[0] = fma2(h0.x, uz2, az[0]);  az[1] = fma2(h0.y, uz2, az[1]);
            az[2] = fma2(h1.x, uz2, az[2]);  az[3] = fma2(h1.y, uz2, az[3]);
            ar[0] = fma2(h0.x, ur2, ar[0]);  ar[1] = fma2(h0.y, ur2, ar[1]);
            ar[2] = fma2(h1.x, ur2, ar[2]);  ar[3] = fma2(h1.y, ur2, ar[3]);
        }
        sred[((0*4 + q)*G + g)*2 + 0] = make_ulonglong2(az[0], az[1]);
        sred[((0*4 + q)*G + g)*2 + 1] = make_ulonglong2(az[2], az[3]);
        sred[((1*4 + q)*G + g)*2 + 0] = make_ulonglong2(ar[0], ar[1]);
        sred[((1*4 + q)*G + g)*2 + 1] = make_ulonglong2(ar[2], ar[3]);
        __syncthreads();

        if (tid < 512) {
            const int col = tid & (G-1), half = tid >> 8;
            ulonglong2 zp = sred[((0*4+0)*G + col)*2 + half];
            ulonglong2 rp = sred[((1*4+0)*G + col)*2 + half];
            #pragma unroll
            for (int qq = 1; qq < 4; qq++) {
                zp = add2v(zp, sred[((0*4+qq)*G + col)*2 + half]);
                rp = add2v(rp, sred[((1*4+qq)*G + col)*2 + half]);
            }
            const size_t pbase = (((size_t)t*3)*G + col)*B + b0 + 4*half;
            zp = add2v(zp, *(const ulonglong2*)&g_proj[pbase]);
            rp = add2v(rp, *(const ulonglong2*)&g_proj[pbase + (size_t)G*B]);
            pn = *(const ulonglong2*)&g_proj[pbase + (size_t)2*G*B];

            ulonglong2 hold = sh[col*2 + half];
            unpack2(hold.x, hf[0], hf[1]); unpack2(hold.y, hf[2], hf[3]);
            float zraw[4], rraw[4];
            unpack2(zp.x, zraw[0], zraw[1]); unpack2(zp.y, zraw[2], zraw[3]);
            unpack2(rp.x, rraw[0], rraw[1]); unpack2(rp.y, rraw[2], rraw[3]);
            float rh[4];
            #pragma unroll
            for (int e = 0; e < 4; e++) {
                zf[e] = fast_sigmoid(zraw[e]);
                rh[e] = fast_sigmoid(rraw[e]) * hf[e];
            }
            srh[col*2 + half] = make_ulonglong2(pack2(rh[0], rh[1]), pack2(rh[2], rh[3]));
        }
        __syncthreads();

        // pass 2: partial (r*h)@Ugn
        ull an[4] = {0,0,0,0};
        #pragma unroll 4
        for (int i = i0; i < i0 + G/4; i++) {
            ull un2 = pack1(Ugn[i*G + g]);
            ulonglong2 s0 = srh[i*2 + 0];
            ulonglong2 s1 = srh[i*2 + 1];
            an[0] = fma2(s0.x, un2, an[0]);  an[1] = fma2(s0.y, un2, an[1]);
            an[2] = fma2(s1.x, un2, an[2]);  an[3] = fma2(s1.y, un2, an[3]);
        }
        sred[((0*4 + q)*G + g)*2 + 0] = make_ulonglong2(an[0], an[1]);
        sred[((0*4 + q)*G + g)*2 + 1] = make_ulonglong2(an[2], an[3]);
        __syncthreads();

        if (tid < 512) {
            const int col = tid & (G-1), half = tid >> 8;
            ulonglong2 ap = sred[((0*4+0)*G + col)*2 + half];
            #pragma unroll
            for (int qq = 1; qq < 4; qq++)
                ap = add2v(ap, sred[((0*4+qq)*G + col)*2 + half]);
            ap = add2v(ap, pn);
            float af[4];
            unpack2(ap.x, af[0], af[1]); unpack2(ap.y, af[2], af[3]);
            float hn[4];
            #pragma unroll
            for (int e = 0; e < 4; e++)
                hn[e] = (1.f - zf[e]) * fast_tanh(af[e]) + zf[e] * hf[e];
            sh[col*2 + half] = make_ulonglong2(pack2(hn[0], hn[1]), pack2(hn[2], hn[3]));
        }
        __syncthreads();
    }

    if (tid < 512) {
        const int col = tid & (G-1), half = tid >> 8;
        ulonglong2 hv = sh[col*2 + half];
        float hfv[4];
        unpack2(hv.x, hfv[0], hfv[1]); unpack2(hv.y, hfv[2], hfv[3]);
        #pragma unroll
        for (int e = 0; e < 4; e++)
            g_h[(size_t)(b0 + 4*half + e)*G + col] = hfv[e];
    }
}

// ---------------------------------------------------------------------------
// Classifier
// ---------------------------------------------------------------------------
__global__ __launch_bounds__(64) void cls_kernel(
    const float* __restrict__ W1, const float* __restrict__ b1,
    const float* __restrict__ W2, const float* __restrict__ b2,
    float* __restrict__ out)
{
    __shared__ float wsum[2];
    const int b = blockIdx.x;
    const int j = threadIdx.x;

    const float* hb = g_h + (size_t)b*G;
    float acc = b1[j];
    #pragma unroll 8
    for (int i = 0; i < G; i++) acc += hb[i] * W1[i*64 + j];
    float hid = fmaxf(acc, 0.f);
    float v = hid * W2[j];
    #pragma unroll
    for (int o = 16; o > 0; o >>= 1) v += __shfl_down_sync(0xffffffffu, v, o);
    if ((j & 31) == 0) wsum[j >> 5] = v;
    __syncthreads();
    if (j == 0) out[b] = fast_sigmoid(wsum[0] + wsum[1] + b2[0]);
}

extern "C" void kernel_launch(void* const* d_in, const int* in_sizes, int n_in,
                              void* d_out, int out_size)
{
    const float* x    = (const float*)d_in[0];
    const float* adj  = (const float*)d_in[1];
    const float* W_fi = (const float*)d_in[2];
    const float* b_fi = (const float*)d_in[3];
    const float* Wz   = (const float*)d_in[4];
    const float* Uz   = (const float*)d_in[5];
    const float* bz   = (const float*)d_in[6];
    const float* Wr   = (const float*)d_in[7];
    const float* Ur   = (const float*)d_in[8];
    const float* br   = (const float*)d_in[9];
    const float* Wh   = (const float*)d_in[10];
    const float* Uh   = (const float*)d_in[11];
    const float* bh   = (const float*)d_in[12];
    const float* Wgp  = (const float*)d_in[13];
    const float* bgp  = (const float*)d_in[14];
    const float* Wgz  = (const float*)d_in[15];
    const float* Ugz  = (const float*)d_in[16];
    const float* bgz  = (const float*)d_in[17];
    const float* Wgr  = (const float*)d_in[18];
    const float* Ugr  = (const float*)d_in[19];
    const float* bgr  = (const float*)d_in[20];
    const float* Wgn  = (const float*)d_in[21];
    const float* Ugn  = (const float*)d_in[22];
    const float* bgn  = (const float*)d_in[23];
    const float* W1   = (const float*)d_in[24];
    const float* b1   = (const float*)d_in[25];
    const float* W2   = (const float*)d_in[26];
    const float* b2   = (const float*)d_in[27];
    float* out = (float*)d_out;

    const int recur_smem = (512 + 512 + 2*4*G*2) * (int)sizeof(ulonglong2);  // 81,920 B
    static int attr_done = 0;
    if (!attr_done) {
        cudaFuncSetAttribute(recur_kernel,
                             cudaFuncAttributeMaxDynamicSharedMemorySize, recur_smem);
        attr_done = 1;
    }

    wcomb_kernel<<<dim3(KH, 3), G>>>(Wgp, bgp, Wgz, bgz, Wgr, bgr, Wgn, bgn);
    gnn_kernel<<<dim3(B/E4, T), KH>>>(x, adj, W_fi, b_fi,
                                      Wz, Uz, bz, Wr, Ur, br, Wh, Uh, bh);
    proj_kernel<<<dim3(B/NBP, T), G>>>();
    recur_kernel<<<B/GB, RT, recur_smem>>>(Ugz, Ugr, Ugn);
    cls_kernel<<<B, 64>>>(W1, b1, W2, b2, out);
}